// round 2
// baseline (speedup 1.0000x reference)
#include <cuda_runtime.h>
#include <cstdint>
#include <cstddef>

// ---------------- problem constants (max sizes for static scratch) ----------------
#define NMAX 50000
#define EMAX 800000
#define ETMAX (EMAX + NMAX)

// ---------------- device scratch (static __device__ arrays are allowed) ------------
__device__ int   g_is64;
__device__ int   g_src[ETMAX];
__device__ int   g_dst[ETMAX];
__device__ int   g_cnt[NMAX];
__device__ int   g_rowptr[NMAX + 1];
__device__ int   g_cursor[NMAX];
__device__ int   g_part[64];
__device__ int   g_esrc[ETMAX];
__device__ float g_h[(size_t)NMAX * 256];    // GEMM output / per-layer features
__device__ float g_buf[(size_t)NMAX * 256];  // layer ping-pong buffer
__device__ float g_as[(size_t)NMAX * 4];     // per-node src scores [N,H]
__device__ float g_ad[(size_t)NMAX * 4];     // per-node dst scores [N,H]

// =============================== CSR construction ==================================

// Detect int64 vs int32 edge_index: for int64 values < 2^31, every odd 32-bit word
// (high half) is zero. Single block, deterministic.
__global__ void detect_kernel(const unsigned int* __restrict__ p, int E) {
    __shared__ int sor;
    if (threadIdx.x == 0) sor = 0;
    __syncthreads();
    int ns = E < 2048 ? E : 2048;
    unsigned int acc = 0;
    for (int i = threadIdx.x; i < ns; i += blockDim.x) acc |= p[2 * i + 1];
    if (acc) atomicOr(&sor, 1);
    __syncthreads();
    if (threadIdx.x == 0) g_is64 = (sor == 0) ? 1 : 0;
}

__global__ void zero_cnt_kernel(int n) {
    int i = blockIdx.x * blockDim.x + threadIdx.x;
    if (i < n) g_cnt[i] = 0;
}

// Decode edges (+ self loops) and histogram destination degrees.
__global__ void decode_count_kernel(const void* __restrict__ eptr, int E, int n) {
    int i = blockIdx.x * blockDim.x + threadIdx.x;
    int ET = E + n;
    if (i >= ET) return;
    int s, d;
    if (i >= E) {
        s = d = i - E;  // self loop
    } else if (g_is64) {
        const long long* p = (const long long*)eptr;
        s = (int)p[i];
        d = (int)p[(size_t)E + i];
    } else {
        const int* p = (const int*)eptr;
        s = p[i];
        d = p[E + i];
    }
    g_src[i] = s;
    g_dst[i] = d;
    atomicAdd(&g_cnt[d], 1);
}

// Block-level inclusive scan (Hillis-Steele over 1024).
__global__ void scan1_kernel(int n) {
    __shared__ int sh[1024];
    int i = blockIdx.x * 1024 + threadIdx.x;
    int v = (i < n) ? g_cnt[i] : 0;
    sh[threadIdx.x] = v;
    __syncthreads();
    for (int o = 1; o < 1024; o <<= 1) {
        int t = (threadIdx.x >= o) ? sh[threadIdx.x - o] : 0;
        __syncthreads();
        sh[threadIdx.x] += t;
        __syncthreads();
    }
    if (i < n) g_rowptr[i + 1] = sh[threadIdx.x];
    if (threadIdx.x == 1023) g_part[blockIdx.x] = sh[1023];
}

__global__ void scan2_kernel(int nb) {
    // serial exclusive scan over <=64 block sums
    int acc = 0;
    for (int i = 0; i < nb; i++) {
        int t = g_part[i];
        g_part[i] = acc;
        acc += t;
    }
}

__global__ void scan3_kernel(int n) {
    int i = blockIdx.x * blockDim.x + threadIdx.x;
    if (i < n) g_rowptr[i + 1] += g_part[i >> 10];
    if (i == 0) g_rowptr[0] = 0;
}

__global__ void cursor_kernel(int n) {
    int i = blockIdx.x * blockDim.x + threadIdx.x;
    if (i < n) g_cursor[i] = g_rowptr[i];
}

__global__ void scatter_kernel(int ET) {
    int i = blockIdx.x * blockDim.x + threadIdx.x;
    if (i >= ET) return;
    int d = g_dst[i];
    int pos = atomicAdd(&g_cursor[d], 1);
    g_esrc[pos] = g_src[i];
}

// =============================== GEMM (fp32 SIMT) ==================================
// C[M,N] = A[M,256] @ B[256,N]. 64x64 tile, BK=16, 256 threads, 4x4 microtile.
__global__ __launch_bounds__(256) void gemm_kernel(const float* __restrict__ A,
                                                   const float* __restrict__ B,
                                                   float* __restrict__ C, int M, int N) {
    const int K = 256;
    __shared__ float As[16][64];
    __shared__ float Bs[16][64];
    int tid = threadIdx.x;
    int tx = tid & 15, ty = tid >> 4;
    int row0 = blockIdx.x * 64;
    int col0 = blockIdx.y * 64;
    int am = tid >> 2, ak = (tid & 3) * 4;   // A tile: row am (0..63), k4 ak
    int bk = tid >> 4, bn = (tid & 15) * 4;  // B tile: k bk (0..15), col4 bn

    float acc[4][4];
#pragma unroll
    for (int i = 0; i < 4; i++)
#pragma unroll
        for (int j = 0; j < 4; j++) acc[i][j] = 0.f;

    for (int kk = 0; kk < K; kk += 16) {
        float4 av;
        if (row0 + am < M)
            av = *(const float4*)&A[(size_t)(row0 + am) * K + kk + ak];
        else
            av = make_float4(0.f, 0.f, 0.f, 0.f);
        As[ak + 0][am] = av.x;
        As[ak + 1][am] = av.y;
        As[ak + 2][am] = av.z;
        As[ak + 3][am] = av.w;
        float4 bv = *(const float4*)&B[(size_t)(kk + bk) * N + col0 + bn];
        *(float4*)&Bs[bk][bn] = bv;
        __syncthreads();
#pragma unroll
        for (int k = 0; k < 16; k++) {
            float4 a4 = *(const float4*)&As[k][ty * 4];
            float4 b4 = *(const float4*)&Bs[k][tx * 4];
            float a[4] = {a4.x, a4.y, a4.z, a4.w};
            float b[4] = {b4.x, b4.y, b4.z, b4.w};
#pragma unroll
            for (int i = 0; i < 4; i++)
#pragma unroll
                for (int j = 0; j < 4; j++) acc[i][j] += a[i] * b[j];
        }
        __syncthreads();
    }
#pragma unroll
    for (int i = 0; i < 4; i++) {
        int r = row0 + ty * 4 + i;
        if (r < M)
            *(float4*)&C[(size_t)r * N + col0 + tx * 4] =
                make_float4(acc[i][0], acc[i][1], acc[i][2], acc[i][3]);
    }
}

// ====================== per-node attention scores (warp/node) ======================
template <int H, int C>
__global__ __launch_bounds__(256) void scores_kernel(const float* __restrict__ a_s,
                                                     const float* __restrict__ a_d, int n) {
    const int F = H * C, VC = F / 32, G = C / VC, NV4 = VC / 4;
    int gid = blockIdx.x * blockDim.x + threadIdx.x;
    int node = gid >> 5, lane = gid & 31;
    if (node >= n) return;
    const float4* hp = (const float4*)g_h + (size_t)node * (F / 4) + lane * NV4;
    const float4* ap = (const float4*)a_s + lane * NV4;
    const float4* dp = (const float4*)a_d + lane * NV4;
    float ss = 0.f, sd = 0.f;
#pragma unroll
    for (int i = 0; i < NV4; i++) {
        float4 h4 = hp[i], a4 = ap[i], d4 = dp[i];
        ss += h4.x * a4.x + h4.y * a4.y + h4.z * a4.z + h4.w * a4.w;
        sd += h4.x * d4.x + h4.y * d4.y + h4.z * d4.z + h4.w * d4.w;
    }
#pragma unroll
    for (int o = 1; o < G; o <<= 1) {
        ss += __shfl_xor_sync(0xffffffffu, ss, o);
        sd += __shfl_xor_sync(0xffffffffu, sd, o);
    }
    if ((lane & (G - 1)) == 0) {
        g_as[node * H + lane / G] = ss;
        g_ad[node * H + lane / G] = sd;
    }
}

// ================== softmax + gather-aggregate (warp per dst node) =================
template <int H, int C>
__global__ __launch_bounds__(256) void agg_kernel(const float* __restrict__ bias,
                                                  float* __restrict__ out, int n, int do_elu) {
    const int F = H * C, VC = F / 32, G = C / VC, NV4 = VC / 4;
    int gid = blockIdx.x * blockDim.x + threadIdx.x;
    int node = gid >> 5, lane = gid & 31;
    if (node >= n) return;
    int start = g_rowptr[node], end = g_rowptr[node + 1];

    float adl[H], m[H], den[H];
#pragma unroll
    for (int h = 0; h < H; h++) {
        adl[h] = g_ad[node * H + h];
        m[h] = -3.4e38f;
        den[h] = 0.f;
    }
    // pass 1: per-head max (edges strided over lanes)
    for (int e = start + lane; e < end; e += 32) {
        int s = g_esrc[e];
#pragma unroll
        for (int h = 0; h < H; h++) {
            float v = g_as[s * H + h] + adl[h];
            v = v > 0.f ? v : 0.2f * v;
            m[h] = fmaxf(m[h], v);
        }
    }
#pragma unroll
    for (int o = 16; o > 0; o >>= 1)
#pragma unroll
        for (int h = 0; h < H; h++) m[h] = fmaxf(m[h], __shfl_xor_sync(0xffffffffu, m[h], o));
    // pass 2: denominator
    for (int e = start + lane; e < end; e += 32) {
        int s = g_esrc[e];
#pragma unroll
        for (int h = 0; h < H; h++) {
            float v = g_as[s * H + h] + adl[h];
            v = v > 0.f ? v : 0.2f * v;
            den[h] += __expf(v - m[h]);
        }
    }
#pragma unroll
    for (int o = 16; o > 0; o >>= 1)
#pragma unroll
        for (int h = 0; h < H; h++) den[h] += __shfl_xor_sync(0xffffffffu, den[h], o);

    int myh = lane / G;  // head owning this lane's channels
    float mh = m[0], dh = den[0], adh = adl[0];
#pragma unroll
    for (int h = 1; h < H; h++)
        if (myh == h) { mh = m[h]; dh = den[h]; adh = adl[h]; }
    float inv = 1.f / (dh + 1e-16f);

    float4 acc[NV4];
#pragma unroll
    for (int i = 0; i < NV4; i++) acc[i] = make_float4(0.f, 0.f, 0.f, 0.f);
    const float4* HB = (const float4*)g_h;
    // pass 3: whole warp streams each incoming edge's feature row
    for (int e = start; e < end; e++) {
        int s = g_esrc[e];
        float v = g_as[s * H + myh] + adh;
        v = v > 0.f ? v : 0.2f * v;
        float alpha = __expf(v - mh) * inv;
        const float4* hp = HB + (size_t)s * (F / 4) + lane * NV4;
#pragma unroll
        for (int i = 0; i < NV4; i++) {
            float4 hv = hp[i];
            acc[i].x += alpha * hv.x;
            acc[i].y += alpha * hv.y;
            acc[i].z += alpha * hv.z;
            acc[i].w += alpha * hv.w;
        }
    }
    const float4* bp = (const float4*)bias + lane * NV4;
    float4* op = (float4*)out + (size_t)node * (F / 4) + lane * NV4;
#pragma unroll
    for (int i = 0; i < NV4; i++) {
        float4 b4 = bp[i];
        float4 r = make_float4(acc[i].x + b4.x, acc[i].y + b4.y, acc[i].z + b4.z, acc[i].w + b4.w);
        if (do_elu) {
            r.x = r.x > 0.f ? r.x : __expf(r.x) - 1.f;
            r.y = r.y > 0.f ? r.y : __expf(r.y) - 1.f;
            r.z = r.z > 0.f ? r.z : __expf(r.z) - 1.f;
            r.w = r.w > 0.f ? r.w : __expf(r.w) - 1.f;
        }
        op[i] = r;
    }
}

// =================================== host side =====================================
extern "C" void kernel_launch(void* const* d_in, const int* in_sizes, int n_in,
                              void* d_out, int out_size) {
    const float* x = (const float*)d_in[0];
    const void* eidx = d_in[1];
    const float* W1 = (const float*)d_in[2];
    const float* as1 = (const float*)d_in[3];
    const float* ad1 = (const float*)d_in[4];
    const float* b1 = (const float*)d_in[5];
    const float* W2 = (const float*)d_in[6];
    const float* as2 = (const float*)d_in[7];
    const float* ad2 = (const float*)d_in[8];
    const float* b2 = (const float*)d_in[9];
    const float* W3 = (const float*)d_in[10];
    const float* as3 = (const float*)d_in[11];
    const float* ad3 = (const float*)d_in[12];
    const float* b3 = (const float*)d_in[13];

    int n = in_sizes[0] / 256;
    int E = in_sizes[1] / 2;
    int ET = E + n;

    float *hbuf = nullptr, *bufA = nullptr;
    cudaGetSymbolAddress((void**)&hbuf, g_h);
    cudaGetSymbolAddress((void**)&bufA, g_buf);

    int nb = (n + 1023) / 1024;

    // ---- CSR build (graph identical across layers) ----
    detect_kernel<<<1, 1024>>>((const unsigned int*)eidx, E);
    zero_cnt_kernel<<<(n + 255) / 256, 256>>>(n);
    decode_count_kernel<<<(ET + 255) / 256, 256>>>(eidx, E, n);
    scan1_kernel<<<nb, 1024>>>(n);
    scan2_kernel<<<1, 1>>>(nb);
    scan3_kernel<<<(n + 255) / 256, 256>>>(n);
    cursor_kernel<<<(n + 255) / 256, 256>>>(n);
    scatter_kernel<<<(ET + 255) / 256, 256>>>(ET);

    int warp_blocks = (n * 32 + 255) / 256;

    // ---- layer 1: 256 -> 4x64, elu ----
    gemm_kernel<<<dim3((n + 63) / 64, 4), 256>>>(x, W1, hbuf, n, 256);
    scores_kernel<4, 64><<<warp_blocks, 256>>>(as1, ad1, n);
    agg_kernel<4, 64><<<warp_blocks, 256>>>(b1, bufA, n, 1);

    // ---- layer 2: 256 -> 4x64, elu ----
    gemm_kernel<<<dim3((n + 63) / 64, 4), 256>>>(bufA, W2, hbuf, n, 256);
    scores_kernel<4, 64><<<warp_blocks, 256>>>(as2, ad2, n);
    agg_kernel<4, 64><<<warp_blocks, 256>>>(b2, bufA, n, 1);

    // ---- layer 3: 256 -> 1x128, no activation, write d_out ----
    gemm_kernel<<<dim3((n + 63) / 64, 2), 256>>>(bufA, W3, hbuf, n, 128);
    scores_kernel<1, 128><<<warp_blocks, 256>>>(as3, ad3, n);
    agg_kernel<1, 128><<<warp_blocks, 256>>>(b3, (float*)d_out, n, 0);
}

// round 6
// speedup vs baseline: 1.4227x; 1.4227x over previous
#include <cuda_runtime.h>
#include <cuda_bf16.h>
#include <cstdint>
#include <cstddef>

// ---------------- problem constants ----------------
#define NMAX 50000
#define EMAX 800000
#define ETMAX (EMAX + NMAX)

// ---------------- device scratch ----------------
__device__ int   g_is64;
__device__ int   g_src[ETMAX];
__device__ int   g_dst[ETMAX];
__device__ int   g_cnt[NMAX];
__device__ int   g_rowptr[NMAX + 1];
__device__ int   g_cursor[NMAX];
__device__ int   g_part[64];
__device__ int   g_esrc[ETMAX];
__device__ float g_h[(size_t)NMAX * 256];    // GEMM output / per-layer features
__device__ float g_buf[(size_t)NMAX * 256];  // layer ping-pong buffer
__device__ float g_as[(size_t)NMAX * 4];     // per-node src scores [N,H]
__device__ float g_ad[(size_t)NMAX * 4];     // per-node dst scores [N,H]
__device__ __nv_bfloat16 g_ahi[(size_t)NMAX * 256];  // A split hi
__device__ __nv_bfloat16 g_alo[(size_t)NMAX * 256];  // A split lo
__device__ __nv_bfloat16 g_bhi[256 * 256];           // W^T split hi [N,K]
__device__ __nv_bfloat16 g_blo[256 * 256];           // W^T split lo [N,K]

// =============================== CSR construction ==================================
__global__ void detect_kernel(const unsigned int* __restrict__ p, int E) {
    __shared__ int sor;
    if (threadIdx.x == 0) sor = 0;
    __syncthreads();
    int ns = E < 2048 ? E : 2048;
    unsigned int acc = 0;
    for (int i = threadIdx.x; i < ns; i += blockDim.x) acc |= p[2 * i + 1];
    if (acc) atomicOr(&sor, 1);
    __syncthreads();
    if (threadIdx.x == 0) g_is64 = (sor == 0) ? 1 : 0;
}
__global__ void zero_cnt_kernel(int n) {
    int i = blockIdx.x * blockDim.x + threadIdx.x;
    if (i < n) g_cnt[i] = 0;
}
__global__ void decode_count_kernel(const void* __restrict__ eptr, int E, int n) {
    int i = blockIdx.x * blockDim.x + threadIdx.x;
    int ET = E + n;
    if (i >= ET) return;
    int s, d;
    if (i >= E) {
        s = d = i - E;
    } else if (g_is64) {
        const long long* p = (const long long*)eptr;
        s = (int)p[i];
        d = (int)p[(size_t)E + i];
    } else {
        const int* p = (const int*)eptr;
        s = p[i];
        d = p[E + i];
    }
    g_src[i] = s;
    g_dst[i] = d;
    atomicAdd(&g_cnt[d], 1);
}
__global__ void scan1_kernel(int n) {
    __shared__ int sh[1024];
    int i = blockIdx.x * 1024 + threadIdx.x;
    int v = (i < n) ? g_cnt[i] : 0;
    sh[threadIdx.x] = v;
    __syncthreads();
    for (int o = 1; o < 1024; o <<= 1) {
        int t = (threadIdx.x >= o) ? sh[threadIdx.x - o] : 0;
        __syncthreads();
        sh[threadIdx.x] += t;
        __syncthreads();
    }
    if (i < n) g_rowptr[i + 1] = sh[threadIdx.x];
    if (threadIdx.x == 1023) g_part[blockIdx.x] = sh[1023];
}
__global__ void scan2_kernel(int nb) {
    int acc = 0;
    for (int i = 0; i < nb; i++) {
        int t = g_part[i];
        g_part[i] = acc;
        acc += t;
    }
}
__global__ void scan3_kernel(int n) {
    int i = blockIdx.x * blockDim.x + threadIdx.x;
    if (i < n) g_rowptr[i + 1] += g_part[i >> 10];
    if (i == 0) g_rowptr[0] = 0;
}
__global__ void cursor_kernel(int n) {
    int i = blockIdx.x * blockDim.x + threadIdx.x;
    if (i < n) g_cursor[i] = g_rowptr[i];
}
__global__ void scatter_kernel(int ET) {
    int i = blockIdx.x * blockDim.x + threadIdx.x;
    if (i >= ET) return;
    int d = g_dst[i];
    int pos = atomicAdd(&g_cursor[d], 1);
    g_esrc[pos] = g_src[i];
}

// ============================ split conversions ==================================
__global__ void asplit_kernel(const float* __restrict__ src, int count4) {
    int i = blockIdx.x * blockDim.x + threadIdx.x;
    if (i >= count4) return;
    float4 v = ((const float4*)src)[i];
    __nv_bfloat16 h0 = __float2bfloat16(v.x), h1 = __float2bfloat16(v.y);
    __nv_bfloat16 h2 = __float2bfloat16(v.z), h3 = __float2bfloat16(v.w);
    __nv_bfloat16 l0 = __float2bfloat16(v.x - __bfloat162float(h0));
    __nv_bfloat16 l1 = __float2bfloat16(v.y - __bfloat162float(h1));
    __nv_bfloat16 l2 = __float2bfloat16(v.z - __bfloat162float(h2));
    __nv_bfloat16 l3 = __float2bfloat16(v.w - __bfloat162float(h3));
    __nv_bfloat162* hp = (__nv_bfloat162*)g_ahi;
    __nv_bfloat162* lp = (__nv_bfloat162*)g_alo;
    hp[2 * i] = __nv_bfloat162(h0, h1);
    hp[2 * i + 1] = __nv_bfloat162(h2, h3);
    lp[2 * i] = __nv_bfloat162(l0, l1);
    lp[2 * i + 1] = __nv_bfloat162(l2, l3);
}
// W [K=256, N] fp32 -> W^T [N, 256] (hi, lo) bf16
__global__ void wsplit_kernel(const float* __restrict__ W, int N, int total) {
    int t = blockIdx.x * blockDim.x + threadIdx.x;
    if (t >= total) return;
    int k = t & 255, n = t >> 8;
    float v = W[(size_t)k * N + n];
    __nv_bfloat16 h = __float2bfloat16(v);
    g_bhi[n * 256 + k] = h;
    g_blo[n * 256 + k] = __float2bfloat16(v - __bfloat162float(h));
}

// ========================= HMMA split-3 bf16 GEMM ================================
// C[M, ldC] cols [n0, n0+64) = A[M,256] @ W[256, ldC]  (fp32 accum).
// Block 128x64, 8 warps (4x2), warp tile 32x32, BK=32, K_virtual = 3*256.
#define MMA_BF16(d, a, b)                                                              \
    asm volatile(                                                                       \
        "mma.sync.aligned.m16n8k16.row.col.f32.bf16.bf16.f32 "                          \
        "{%0,%1,%2,%3}, {%4,%5,%6,%7}, {%8,%9}, {%0,%1,%2,%3};"                         \
        : "+f"((d)[0]), "+f"((d)[1]), "+f"((d)[2]), "+f"((d)[3])                        \
        : "r"((a)[0]), "r"((a)[1]), "r"((a)[2]), "r"((a)[3]), "r"((b)[0]), "r"((b)[1]))

__global__ __launch_bounds__(256) void hmma_gemm_kernel(float* __restrict__ C, int M, int ldC) {
    // smem K-major, row pitch 40 bf16 (80B) -> conflict-free 32-bit fragment loads
    __shared__ __nv_bfloat16 sAh[128 * 40], sAl[128 * 40];
    __shared__ __nv_bfloat16 sBh[64 * 40], sBl[64 * 40];
    int tid = threadIdx.x, wid = tid >> 5, lane = tid & 31;
    int warp_m = wid & 3, warp_n = wid >> 2;
    int g = lane >> 2, t = lane & 3;
    int m0 = blockIdx.x * 128, n0 = blockIdx.y * 64;

    float acc[2][4][4];
#pragma unroll
    for (int mt = 0; mt < 2; mt++)
#pragma unroll
        for (int nt = 0; nt < 4; nt++)
#pragma unroll
            for (int r = 0; r < 4; r++) acc[mt][nt][r] = 0.f;

    const uint32_t* sAh32 = (const uint32_t*)sAh;
    const uint32_t* sAl32 = (const uint32_t*)sAl;
    const uint32_t* sBh32 = (const uint32_t*)sBh;
    const uint32_t* sBl32 = (const uint32_t*)sBl;

    for (int c = 0; c < 8; c++) {  // K chunks of 32
        int kc = c * 32;
        __syncthreads();
        // A tiles: 128 rows x 4 uint4 = 512 per split
        for (int u = tid; u < 512; u += 256) {
            int row = u >> 2, q = u & 3;
            uint4 vh = make_uint4(0, 0, 0, 0), vl = make_uint4(0, 0, 0, 0);
            if (m0 + row < M) {
                size_t go = (size_t)(m0 + row) * 256 + kc + q * 8;
                vh = *(const uint4*)(g_ahi + go);
                vl = *(const uint4*)(g_alo + go);
            }
            *(uint4*)(sAh + row * 40 + q * 8) = vh;
            *(uint4*)(sAl + row * 40 + q * 8) = vl;
        }
        // B tiles: 64 rows x 4 uint4 = 256 per split
        {
            int u = tid;
            int row = u >> 2, q = u & 3;
            size_t go = (size_t)(n0 + row) * 256 + kc + q * 8;
            *(uint4*)(sBh + row * 40 + q * 8) = *(const uint4*)(g_bhi + go);
            *(uint4*)(sBl + row * 40 + q * 8) = *(const uint4*)(g_blo + go);
        }
        __syncthreads();

#pragma unroll
        for (int kk = 0; kk < 32; kk += 16) {
            uint32_t ah[2][4], al[2][4], bh[4][2], bl[4][2];
#pragma unroll
            for (int mt = 0; mt < 2; mt++) {
                int r0 = warp_m * 32 + mt * 16 + g;
                int base = (r0 * 40 + kk + t * 2) >> 1;       // uint32 index
                int base8 = ((r0 + 8) * 40 + kk + t * 2) >> 1;
                ah[mt][0] = sAh32[base];
                ah[mt][1] = sAh32[base8];
                ah[mt][2] = sAh32[base + 4];
                ah[mt][3] = sAh32[base8 + 4];
                al[mt][0] = sAl32[base];
                al[mt][1] = sAl32[base8];
                al[mt][2] = sAl32[base + 4];
                al[mt][3] = sAl32[base8 + 4];
            }
#pragma unroll
            for (int nt = 0; nt < 4; nt++) {
                int col = warp_n * 32 + nt * 8 + g;
                int base = (col * 40 + kk + t * 2) >> 1;
                bh[nt][0] = sBh32[base];
                bh[nt][1] = sBh32[base + 4];
                bl[nt][0] = sBl32[base];
                bl[nt][1] = sBl32[base + 4];
            }
#pragma unroll
            for (int mt = 0; mt < 2; mt++)
#pragma unroll
                for (int nt = 0; nt < 4; nt++) {
                    MMA_BF16(acc[mt][nt], ah[mt], bh[nt]);
                    MMA_BF16(acc[mt][nt], ah[mt], bl[nt]);
                    MMA_BF16(acc[mt][nt], al[mt], bh[nt]);
                }
        }
    }

    // epilogue
#pragma unroll
    for (int mt = 0; mt < 2; mt++) {
        int r0 = m0 + warp_m * 32 + mt * 16 + g;
#pragma unroll
        for (int nt = 0; nt < 4; nt++) {
            int col = n0 + warp_n * 32 + nt * 8 + t * 2;
            if (r0 < M)
                *(float2*)(C + (size_t)r0 * ldC + col) = make_float2(acc[mt][nt][0], acc[mt][nt][1]);
            if (r0 + 8 < M)
                *(float2*)(C + (size_t)(r0 + 8) * ldC + col) =
                    make_float2(acc[mt][nt][2], acc[mt][nt][3]);
        }
    }
}

// ====================== per-node attention scores (warp/node) ======================
template <int H, int C>
__global__ __launch_bounds__(256) void scores_kernel(const float* __restrict__ a_s,
                                                     const float* __restrict__ a_d, int n) {
    const int F = H * C, VC = F / 32, G = C / VC, NV4 = VC / 4;
    int gid = blockIdx.x * blockDim.x + threadIdx.x;
    int node = gid >> 5, lane = gid & 31;
    if (node >= n) return;
    const float4* hp = (const float4*)g_h + (size_t)node * (F / 4) + lane * NV4;
    const float4* ap = (const float4*)a_s + lane * NV4;
    const float4* dp = (const float4*)a_d + lane * NV4;
    float ss = 0.f, sd = 0.f;
#pragma unroll
    for (int i = 0; i < NV4; i++) {
        float4 h4 = hp[i], a4 = ap[i], d4 = dp[i];
        ss += h4.x * a4.x + h4.y * a4.y + h4.z * a4.z + h4.w * a4.w;
        sd += h4.x * d4.x + h4.y * d4.y + h4.z * d4.z + h4.w * d4.w;
    }
#pragma unroll
    for (int o = 1; o < G; o <<= 1) {
        ss += __shfl_xor_sync(0xffffffffu, ss, o);
        sd += __shfl_xor_sync(0xffffffffu, sd, o);
    }
    if ((lane & (G - 1)) == 0) {
        g_as[node * H + lane / G] = ss;
        g_ad[node * H + lane / G] = sd;
    }
}

// ================== softmax + gather-aggregate (warp per dst node) =================
// Scores are O(1); softmax is shift-invariant, so skip the segment-max pass.
template <int H, int C>
__global__ __launch_bounds__(256) void agg_kernel(const float* __restrict__ bias,
                                                  float* __restrict__ out, int n, int do_elu) {
    const int F = H * C, VC = F / 32, G = C / VC, NV4 = VC / 4;
    int gid = blockIdx.x * blockDim.x + threadIdx.x;
    int node = gid >> 5, lane = gid & 31;
    if (node >= n) return;
    int start = g_rowptr[node], end = g_rowptr[node + 1];

    float adl[H], den[H];
#pragma unroll
    for (int h = 0; h < H; h++) {
        adl[h] = g_ad[node * H + h];
        den[h] = 0.f;
    }
    for (int e = start + lane; e < end; e += 32) {
        int s = g_esrc[e];
#pragma unroll
        for (int h = 0; h < H; h++) {
            float v = g_as[s * H + h] + adl[h];
            v = v > 0.f ? v : 0.2f * v;
            den[h] += __expf(v);
        }
    }
#pragma unroll
    for (int o = 16; o > 0; o >>= 1)
#pragma unroll
        for (int h = 0; h < H; h++) den[h] += __shfl_xor_sync(0xffffffffu, den[h], o);

    int myh = lane / G;
    float dh = den[0], adh = adl[0];
#pragma unroll
    for (int h = 1; h < H; h++)
        if (myh == h) {
            dh = den[h];
            adh = adl[h];
        }
    float inv = 1.f / (dh + 1e-16f);

    float4 acc[NV4];
#pragma unroll
    for (int i = 0; i < NV4; i++) acc[i] = make_float4(0.f, 0.f, 0.f, 0.f);
    const float4* HB = (const float4*)g_h;
    for (int e = start; e < end; e++) {
        int s = g_esrc[e];
        float v = g_as[s * H + myh] + adh;
        v = v > 0.f ? v : 0.2f * v;
        float alpha = __expf(v) * inv;
        const float4* hp = HB + (size_t)s * (F / 4) + lane * NV4;
#pragma unroll
        for (int i = 0; i < NV4; i++) {
            float4 hv = hp[i];
            acc[i].x += alpha * hv.x;
            acc[i].y += alpha * hv.y;
            acc[i].z += alpha * hv.z;
            acc[i].w += alpha * hv.w;
        }
    }
    const float4* bp = (const float4*)bias + lane * NV4;
    float4* op = (float4*)out + (size_t)node * (F / 4) + lane * NV4;
#pragma unroll
    for (int i = 0; i < NV4; i++) {
        float4 b4 = bp[i];
        float4 r = make_float4(acc[i].x + b4.x, acc[i].y + b4.y, acc[i].z + b4.z, acc[i].w + b4.w);
        if (do_elu) {
            r.x = r.x > 0.f ? r.x : __expf(r.x) - 1.f;
            r.y = r.y > 0.f ? r.y : __expf(r.y) - 1.f;
            r.z = r.z > 0.f ? r.z : __expf(r.z) - 1.f;
            r.w = r.w > 0.f ? r.w : __expf(r.w) - 1.f;
        }
        op[i] = r;
    }
}

// =================================== host side =====================================
extern "C" void kernel_launch(void* const* d_in, const int* in_sizes, int n_in,
                              void* d_out, int out_size) {
    const float* x = (const float*)d_in[0];
    const void* eidx = d_in[1];
    const float* W1 = (const float*)d_in[2];
    const float* as1 = (const float*)d_in[3];
    const float* ad1 = (const float*)d_in[4];
    const float* b1 = (const float*)d_in[5];
    const float* W2 = (const float*)d_in[6];
    const float* as2 = (const float*)d_in[7];
    const float* ad2 = (const float*)d_in[8];
    const float* b2 = (const float*)d_in[9];
    const float* W3 = (const float*)d_in[10];
    const float* as3 = (const float*)d_in[11];
    const float* ad3 = (const float*)d_in[12];
    const float* b3 = (const float*)d_in[13];

    int n = in_sizes[0] / 256;
    int E = in_sizes[1] / 2;
    int ET = E + n;

    float *hbuf = nullptr, *bufA = nullptr;
    cudaGetSymbolAddress((void**)&hbuf, g_h);
    cudaGetSymbolAddress((void**)&bufA, g_buf);

    int nb = (n + 1023) / 1024;

    // ---- CSR build (graph identical across layers) ----
    detect_kernel<<<1, 1024>>>((const unsigned int*)eidx, E);
    zero_cnt_kernel<<<(n + 255) / 256, 256>>>(n);
    decode_count_kernel<<<(ET + 255) / 256, 256>>>(eidx, E, n);
    scan1_kernel<<<nb, 1024>>>(n);
    scan2_kernel<<<1, 1>>>(nb);
    scan3_kernel<<<(n + 255) / 256, 256>>>(n);
    cursor_kernel<<<(n + 255) / 256, 256>>>(n);
    scatter_kernel<<<(ET + 255) / 256, 256>>>(ET);

    int warp_blocks = (n * 32 + 255) / 256;
    int cnt4 = n * 64;
    int cblk = (cnt4 + 255) / 256;
    int mtiles = (n + 127) / 128;

    // ---- layer 1: 256 -> 4x64, elu ----
    asplit_kernel<<<cblk, 256>>>(x, cnt4);
    wsplit_kernel<<<(256 * 256 + 255) / 256, 256>>>(W1, 256, 256 * 256);
    hmma_gemm_kernel<<<dim3(mtiles, 4), 256>>>(hbuf, n, 256);
    scores_kernel<4, 64><<<warp_blocks, 256>>>(as1, ad1, n);
    agg_kernel<4, 64><<<warp_blocks, 256>>>(b1, bufA, n, 1);

    // ---- layer 2: 256 -> 4x64, elu ----
    asplit_kernel<<<cblk, 256>>>(bufA, cnt4);
    wsplit_kernel<<<(256 * 256 + 255) / 256, 256>>>(W2, 256, 256 * 256);
    hmma_gemm_kernel<<<dim3(mtiles, 4), 256>>>(hbuf, n, 256);
    scores_kernel<4, 64><<<warp_blocks, 256>>>(as2, ad2, n);
    agg_kernel<4, 64><<<warp_blocks, 256>>>(b2, bufA, n, 1);

    // ---- layer 3: 256 -> 1x128, no activation, write d_out ----
    asplit_kernel<<<cblk, 256>>>(bufA, cnt4);
    wsplit_kernel<<<(256 * 128 + 255) / 256, 256>>>(W3, 128, 256 * 128);
    hmma_gemm_kernel<<<dim3(mtiles, 2), 256>>>(hbuf, n, 128);
    scores_kernel<1, 128><<<warp_blocks, 256>>>(as3, ad3, n);
    agg_kernel<1, 128><<<warp_blocks, 256>>>(b3, (float*)d_out, n, 0);
}

// round 8
// speedup vs baseline: 1.6335x; 1.1482x over previous
#include <cuda_runtime.h>
#include <cuda_bf16.h>
#include <cstdint>
#include <cstddef>

// ---------------- problem constants ----------------
#define NMAX 50000
#define EMAX 800000
#define ETMAX (EMAX + NMAX)

// ---------------- device scratch ----------------
__device__ int   g_is64;
__device__ int   g_src[ETMAX];
__device__ int   g_dst[ETMAX];
__device__ int   g_cnt[NMAX];
__device__ int   g_rowptr[NMAX + 1];
__device__ int   g_cursor[NMAX];
__device__ int   g_part[64];
__device__ int   g_esrc[ETMAX];
__device__ float g_h[(size_t)NMAX * 256];    // GEMM output (per-layer features)
__device__ float g_as[(size_t)NMAX * 4];     // per-node src scores [N,H]
__device__ float g_ad[(size_t)NMAX * 4];     // per-node dst scores [N,H]
__device__ __nv_bfloat16 g_ahi[(size_t)NMAX * 256];  // A split hi (next GEMM input)
__device__ __nv_bfloat16 g_alo[(size_t)NMAX * 256];  // A split lo
__device__ __nv_bfloat16 g_bhi[256 * 256];           // W^T split hi [N,K]
__device__ __nv_bfloat16 g_blo[256 * 256];           // W^T split lo [N,K]

// =============================== CSR construction ==================================
__global__ void detect_kernel(const unsigned int* __restrict__ p, int E) {
    __shared__ int sor;
    if (threadIdx.x == 0) sor = 0;
    __syncthreads();
    int ns = E < 2048 ? E : 2048;
    unsigned int acc = 0;
    for (int i = threadIdx.x; i < ns; i += blockDim.x) acc |= p[2 * i + 1];
    if (acc) atomicOr(&sor, 1);
    __syncthreads();
    if (threadIdx.x == 0) g_is64 = (sor == 0) ? 1 : 0;
}
__global__ void zero_cnt_kernel(int n) {
    int i = blockIdx.x * blockDim.x + threadIdx.x;
    if (i < n) g_cnt[i] = 0;
}
__global__ void decode_count_kernel(const void* __restrict__ eptr, int E, int n) {
    int i = blockIdx.x * blockDim.x + threadIdx.x;
    int ET = E + n;
    if (i >= ET) return;
    int s, d;
    if (i >= E) {
        s = d = i - E;
    } else if (g_is64) {
        const long long* p = (const long long*)eptr;
        s = (int)p[i];
        d = (int)p[(size_t)E + i];
    } else {
        const int* p = (const int*)eptr;
        s = p[i];
        d = p[E + i];
    }
    g_src[i] = s;
    g_dst[i] = d;
    atomicAdd(&g_cnt[d], 1);
}
__global__ void scan1_kernel(int n) {
    __shared__ int sh[1024];
    int i = blockIdx.x * 1024 + threadIdx.x;
    int v = (i < n) ? g_cnt[i] : 0;
    sh[threadIdx.x] = v;
    __syncthreads();
    for (int o = 1; o < 1024; o <<= 1) {
        int t = (threadIdx.x >= o) ? sh[threadIdx.x - o] : 0;
        __syncthreads();
        sh[threadIdx.x] += t;
        __syncthreads();
    }
    if (i < n) g_rowptr[i + 1] = sh[threadIdx.x];
    if (threadIdx.x == 1023) g_part[blockIdx.x] = sh[1023];
}
__global__ void scan2_kernel(int nb) {
    int acc = 0;
    for (int i = 0; i < nb; i++) {
        int t = g_part[i];
        g_part[i] = acc;
        acc += t;
    }
}
__global__ void scan3_kernel(int n) {
    int i = blockIdx.x * blockDim.x + threadIdx.x;
    if (i < n) g_rowptr[i + 1] += g_part[i >> 10];
    if (i == 0) g_rowptr[0] = 0;
}
__global__ void cursor_kernel(int n) {
    int i = blockIdx.x * blockDim.x + threadIdx.x;
    if (i < n) g_cursor[i] = g_rowptr[i];
}
__global__ void scatter_kernel(int ET) {
    int i = blockIdx.x * blockDim.x + threadIdx.x;
    if (i >= ET) return;
    int d = g_dst[i];
    int pos = atomicAdd(&g_cursor[d], 1);
    g_esrc[pos] = g_src[i];
}

// ============================ split conversions ==================================
// fp32 -> (hi, lo) bf16 pair, vectorized x4 (layer-1 input only; layers 2-3 are
// produced pre-split by the fused agg epilogue)
__global__ void asplit_kernel(const float* __restrict__ src, int count4) {
    int i = blockIdx.x * blockDim.x + threadIdx.x;
    if (i >= count4) return;
    float4 v = ((const float4*)src)[i];
    __nv_bfloat16 h0 = __float2bfloat16(v.x), h1 = __float2bfloat16(v.y);
    __nv_bfloat16 h2 = __float2bfloat16(v.z), h3 = __float2bfloat16(v.w);
    __nv_bfloat16 l0 = __float2bfloat16(v.x - __bfloat162float(h0));
    __nv_bfloat16 l1 = __float2bfloat16(v.y - __bfloat162float(h1));
    __nv_bfloat16 l2 = __float2bfloat16(v.z - __bfloat162float(h2));
    __nv_bfloat16 l3 = __float2bfloat16(v.w - __bfloat162float(h3));
    __nv_bfloat162* hp = (__nv_bfloat162*)g_ahi;
    __nv_bfloat162* lp = (__nv_bfloat162*)g_alo;
    hp[2 * i] = __nv_bfloat162(h0, h1);
    hp[2 * i + 1] = __nv_bfloat162(h2, h3);
    lp[2 * i] = __nv_bfloat162(l0, l1);
    lp[2 * i + 1] = __nv_bfloat162(l2, l3);
}
// W [K=256, N] fp32 -> W^T [N, 256] (hi, lo) bf16
__global__ void wsplit_kernel(const float* __restrict__ W, int N, int total) {
    int t = blockIdx.x * blockDim.x + threadIdx.x;
    if (t >= total) return;
    int k = t & 255, n = t >> 8;
    float v = W[(size_t)k * N + n];
    __nv_bfloat16 h = __float2bfloat16(v);
    g_bhi[n * 256 + k] = h;
    g_blo[n * 256 + k] = __float2bfloat16(v - __bfloat162float(h));
}

// ================= HMMA split-3 bf16 GEMM, cp.async double-buffered ================
// C[M, ldC] cols [n0, n0+64) = A[M,256] @ W[256, ldC]  (fp32 accum).
// Block 128x64, 8 warps (4x2), warp tile 32x32, BK=32. D = AhBh + AhBl + AlBh.
#define MMA_BF16(d, a, b)                                                              \
    asm volatile(                                                                       \
        "mma.sync.aligned.m16n8k16.row.col.f32.bf16.bf16.f32 "                          \
        "{%0,%1,%2,%3}, {%4,%5,%6,%7}, {%8,%9}, {%0,%1,%2,%3};"                         \
        : "+f"((d)[0]), "+f"((d)[1]), "+f"((d)[2]), "+f"((d)[3])                        \
        : "r"((a)[0]), "r"((a)[1]), "r"((a)[2]), "r"((a)[3]), "r"((b)[0]), "r"((b)[1]))

__device__ __forceinline__ void cp16(uint32_t dst, const void* src, int sz) {
    asm volatile("cp.async.cg.shared.global [%0], [%1], 16, %2;" :: "r"(dst), "l"(src),
                 "r"(sz) : "memory");
}

// stage layout (bytes): Ah 0 (10240), Al 10240, Bh 20480 (5120), Bl 25600; stage=30720
#define STG_B 30720

__global__ __launch_bounds__(256) void hmma_gemm_kernel(float* __restrict__ C, int M, int ldC) {
    extern __shared__ __nv_bfloat16 sm[];
    int tid = threadIdx.x, wid = tid >> 5, lane = tid & 31;
    int warp_m = wid & 3, warp_n = wid >> 2;
    int g = lane >> 2, t = lane & 3;
    int m0 = blockIdx.x * 128, n0 = blockIdx.y * 64;
    uint32_t sbase = (uint32_t)__cvta_generic_to_shared(sm);

    float acc[2][4][4];
#pragma unroll
    for (int mt = 0; mt < 2; mt++)
#pragma unroll
        for (int nt = 0; nt < 4; nt++)
#pragma unroll
            for (int r = 0; r < 4; r++) acc[mt][nt][r] = 0.f;

    // per-thread load coordinates (A: 2 rows x (hi,lo); B: 1 row x (hi,lo))
    int arow0 = tid >> 2, aq = tid & 3;          // rows tid/4 and tid/4+64
    int brow = tid >> 2, bq = tid & 3;

    auto load_chunk = [&](int c, int stg) {
        int kc = c * 32;
        uint32_t base = sbase + stg * STG_B;
#pragma unroll
        for (int half = 0; half < 2; half++) {
            int row = arow0 + half * 64;
            int gr = m0 + row;
            int sz = (gr < M) ? 16 : 0;
            int grc = (gr < M) ? gr : 0;
            size_t go = (size_t)grc * 256 + kc + aq * 8;
            uint32_t so = base + (uint32_t)(row * 40 + aq * 8) * 2;
            cp16(so, g_ahi + go, sz);
            cp16(so + 10240, g_alo + go, sz);
        }
        {
            size_t go = (size_t)(n0 + brow) * 256 + kc + bq * 8;
            uint32_t so = base + 20480 + (uint32_t)(brow * 40 + bq * 8) * 2;
            cp16(so, g_bhi + go, 16);
            cp16(so + 5120, g_blo + go, 16);
        }
        asm volatile("cp.async.commit_group;" ::: "memory");
    };

    load_chunk(0, 0);

    for (int c = 0; c < 8; c++) {
        int stg = c & 1;
        if (c + 1 < 8) {
            load_chunk(c + 1, stg ^ 1);
            asm volatile("cp.async.wait_group 1;" ::: "memory");
        } else {
            asm volatile("cp.async.wait_group 0;" ::: "memory");
        }
        __syncthreads();

        const uint32_t* S = (const uint32_t*)((const char*)sm + stg * STG_B);
        const uint32_t* SAl = S + 2560;   // +10240B
        const uint32_t* SBh = S + 5120;   // +20480B
        const uint32_t* SBl = S + 6400;   // +25600B
#pragma unroll
        for (int kk = 0; kk < 32; kk += 16) {
            uint32_t ah[2][4], al[2][4], bh[4][2], bl[4][2];
#pragma unroll
            for (int mt = 0; mt < 2; mt++) {
                int r0 = warp_m * 32 + mt * 16 + g;
                int base = (r0 * 40 + kk + t * 2) >> 1;
                int base8 = ((r0 + 8) * 40 + kk + t * 2) >> 1;
                ah[mt][0] = S[base];
                ah[mt][1] = S[base8];
                ah[mt][2] = S[base + 4];
                ah[mt][3] = S[base8 + 4];
                al[mt][0] = SAl[base];
                al[mt][1] = SAl[base8];
                al[mt][2] = SAl[base + 4];
                al[mt][3] = SAl[base8 + 4];
            }
#pragma unroll
            for (int nt = 0; nt < 4; nt++) {
                int col = warp_n * 32 + nt * 8 + g;
                int base = (col * 40 + kk + t * 2) >> 1;
                bh[nt][0] = SBh[base];
                bh[nt][1] = SBh[base + 4];
                bl[nt][0] = SBl[base];
                bl[nt][1] = SBl[base + 4];
            }
#pragma unroll
            for (int mt = 0; mt < 2; mt++)
#pragma unroll
                for (int nt = 0; nt < 4; nt++) {
                    MMA_BF16(acc[mt][nt], ah[mt], bh[nt]);
                    MMA_BF16(acc[mt][nt], ah[mt], bl[nt]);
                    MMA_BF16(acc[mt][nt], al[mt], bh[nt]);
                }
        }
        __syncthreads();  // protect stage before next-next load overwrites it
    }

    // epilogue
#pragma unroll
    for (int mt = 0; mt < 2; mt++) {
        int r0 = m0 + warp_m * 32 + mt * 16 + g;
#pragma unroll
        for (int nt = 0; nt < 4; nt++) {
            int col = n0 + warp_n * 32 + nt * 8 + t * 2;
            if (r0 < M)
                *(float2*)(C + (size_t)r0 * ldC + col) = make_float2(acc[mt][nt][0], acc[mt][nt][1]);
            if (r0 + 8 < M)
                *(float2*)(C + (size_t)(r0 + 8) * ldC + col) =
                    make_float2(acc[mt][nt][2], acc[mt][nt][3]);
        }
    }
}

// ====================== per-node attention scores (warp/node) ======================
template <int H, int C>
__global__ __launch_bounds__(256) void scores_kernel(const float* __restrict__ a_s,
                                                     const float* __restrict__ a_d, int n) {
    const int F = H * C, VC = F / 32, G = C / VC, NV4 = VC / 4;
    int gid = blockIdx.x * blockDim.x + threadIdx.x;
    int node = gid >> 5, lane = gid & 31;
    if (node >= n) return;
    const float4* hp = (const float4*)g_h + (size_t)node * (F / 4) + lane * NV4;
    const float4* ap = (const float4*)a_s + lane * NV4;
    const float4* dp = (const float4*)a_d + lane * NV4;
    float ss = 0.f, sd = 0.f;
#pragma unroll
    for (int i = 0; i < NV4; i++) {
        float4 h4 = hp[i], a4 = ap[i], d4 = dp[i];
        ss += h4.x * a4.x + h4.y * a4.y + h4.z * a4.z + h4.w * a4.w;
        sd += h4.x * d4.x + h4.y * d4.y + h4.z * d4.z + h4.w * d4.w;
    }
#pragma unroll
    for (int o = 1; o < G; o <<= 1) {
        ss += __shfl_xor_sync(0xffffffffu, ss, o);
        sd += __shfl_xor_sync(0xffffffffu, sd, o);
    }
    if ((lane & (G - 1)) == 0) {
        g_as[node * H + lane / G] = ss;
        g_ad[node * H + lane / G] = sd;
    }
}

// ============== single-pass softmax + gather-aggregate (warp per node) =============
// out = (sum_e exp(lrelu(as[s]+ad[d])) * h[s]) / (sum_e exp(.) + eps)
// No max-shift needed (scores O(1)); normalization is a pure post-scale, so the
// denominator accumulates in the SAME edge pass as the weighted features.
// MODE 0: fp32 out (+bias). MODE 1: bias+ELU then split-write bf16 hi/lo to g_ahi/g_alo.
template <int H, int C, int MODE>
__global__ __launch_bounds__(256) void agg_kernel(const float* __restrict__ bias,
                                                  float* __restrict__ out, int n) {
    const int F = H * C, VC = F / 32, G = C / VC, NV4 = VC / 4;
    int gid = blockIdx.x * blockDim.x + threadIdx.x;
    int node = gid >> 5, lane = gid & 31;
    if (node >= n) return;
    int start = g_rowptr[node], end = g_rowptr[node + 1];
    int myh = lane / G;
    float adh = g_ad[node * H + myh];

    float den = 0.f;
    float4 acc[NV4];
#pragma unroll
    for (int i = 0; i < NV4; i++) acc[i] = make_float4(0.f, 0.f, 0.f, 0.f);
    const float4* HB = (const float4*)g_h;

    int e = start;
    for (; e + 1 < end; e += 2) {  // 2-edge unroll: batch the gathers for MLP
        int s0 = g_esrc[e], s1 = g_esrc[e + 1];
        float v0 = g_as[s0 * H + myh] + adh;
        float v1 = g_as[s1 * H + myh] + adh;
        const float4* hp0 = HB + (size_t)s0 * (F / 4) + lane * NV4;
        const float4* hp1 = HB + (size_t)s1 * (F / 4) + lane * NV4;
        float4 t0[NV4], t1[NV4];
#pragma unroll
        for (int i = 0; i < NV4; i++) {
            t0[i] = hp0[i];
            t1[i] = hp1[i];
        }
        v0 = v0 > 0.f ? v0 : 0.2f * v0;
        v1 = v1 > 0.f ? v1 : 0.2f * v1;
        float w0 = __expf(v0), w1 = __expf(v1);
        den += w0 + w1;
#pragma unroll
        for (int i = 0; i < NV4; i++) {
            acc[i].x += w0 * t0[i].x + w1 * t1[i].x;
            acc[i].y += w0 * t0[i].y + w1 * t1[i].y;
            acc[i].z += w0 * t0[i].z + w1 * t1[i].z;
            acc[i].w += w0 * t0[i].w + w1 * t1[i].w;
        }
    }
    if (e < end) {
        int s = g_esrc[e];
        float v = g_as[s * H + myh] + adh;
        v = v > 0.f ? v : 0.2f * v;
        float w = __expf(v);
        den += w;
        const float4* hp = HB + (size_t)s * (F / 4) + lane * NV4;
#pragma unroll
        for (int i = 0; i < NV4; i++) {
            float4 hv = hp[i];
            acc[i].x += w * hv.x;
            acc[i].y += w * hv.y;
            acc[i].z += w * hv.z;
            acc[i].w += w * hv.w;
        }
    }
    float inv = 1.f / (den + 1e-16f);

    const float4* bp = (const float4*)bias + lane * NV4;
#pragma unroll
    for (int i = 0; i < NV4; i++) {
        float4 b4 = bp[i];
        float4 r = make_float4(acc[i].x * inv + b4.x, acc[i].y * inv + b4.y,
                               acc[i].z * inv + b4.z, acc[i].w * inv + b4.w);
        if (MODE == 0) {
            ((float4*)out)[(size_t)node * (F / 4) + lane * NV4 + i] = r;
        } else {
            // ELU then split to bf16 hi/lo (next layer's GEMM input)
            r.x = r.x > 0.f ? r.x : __expf(r.x) - 1.f;
            r.y = r.y > 0.f ? r.y : __expf(r.y) - 1.f;
            r.z = r.z > 0.f ? r.z : __expf(r.z) - 1.f;
            r.w = r.w > 0.f ? r.w : __expf(r.w) - 1.f;
            __nv_bfloat16 h0 = __float2bfloat16(r.x), h1 = __float2bfloat16(r.y);
            __nv_bfloat16 h2 = __float2bfloat16(r.z), h3 = __float2bfloat16(r.w);
            __nv_bfloat16 l0 = __float2bfloat16(r.x - __bfloat162float(h0));
            __nv_bfloat16 l1 = __float2bfloat16(r.y - __bfloat162float(h1));
            __nv_bfloat16 l2 = __float2bfloat16(r.z - __bfloat162float(h2));
            __nv_bfloat16 l3 = __float2bfloat16(r.w - __bfloat162float(h3));
            size_t ch = (size_t)node * F + lane * VC + i * 4;
            *(__nv_bfloat162*)(g_ahi + ch) = __nv_bfloat162(h0, h1);
            *(__nv_bfloat162*)(g_ahi + ch + 2) = __nv_bfloat162(h2, h3);
            *(__nv_bfloat162*)(g_alo + ch) = __nv_bfloat162(l0, l1);
            *(__nv_bfloat162*)(g_alo + ch + 2) = __nv_bfloat162(l2, l3);
        }
    }
}

// =================================== host side =====================================
extern "C" void kernel_launch(void* const* d_in, const int* in_sizes, int n_in,
                              void* d_out, int out_size) {
    const float* x = (const float*)d_in[0];
    const void* eidx = d_in[1];
    const float* W1 = (const float*)d_in[2];
    const float* as1 = (const float*)d_in[3];
    const float* ad1 = (const float*)d_in[4];
    const float* b1 = (const float*)d_in[5];
    const float* W2 = (const float*)d_in[6];
    const float* as2 = (const float*)d_in[7];
    const float* ad2 = (const float*)d_in[8];
    const float* b2 = (const float*)d_in[9];
    const float* W3 = (const float*)d_in[10];
    const float* as3 = (const float*)d_in[11];
    const float* ad3 = (const float*)d_in[12];
    const float* b3 = (const float*)d_in[13];

    int n = in_sizes[0] / 256;
    int E = in_sizes[1] / 2;
    int ET = E + n;

    float* hbuf = nullptr;
    cudaGetSymbolAddress((void**)&hbuf, g_h);

    // unconditional (no static guards) — host-side attr set, capture-safe
    cudaFuncSetAttribute(hmma_gemm_kernel, cudaFuncAttributeMaxDynamicSharedMemorySize,
                         2 * STG_B);

    int nb = (n + 1023) / 1024;

    // ---- CSR build (graph identical across layers) ----
    detect_kernel<<<1, 1024>>>((const unsigned int*)eidx, E);
    zero_cnt_kernel<<<(n + 255) / 256, 256>>>(n);
    decode_count_kernel<<<(ET + 255) / 256, 256>>>(eidx, E, n);
    scan1_kernel<<<nb, 1024>>>(n);
    scan2_kernel<<<1, 1>>>(nb);
    scan3_kernel<<<(n + 255) / 256, 256>>>(n);
    cursor_kernel<<<(n + 255) / 256, 256>>>(n);
    scatter_kernel<<<(ET + 255) / 256, 256>>>(ET);

    int warp_blocks = (n * 32 + 255) / 256;
    int cnt4 = n * 64;
    int cblk = (cnt4 + 255) / 256;
    int mtiles = (n + 127) / 128;

    // ---- layer 1: 256 -> 4x64, elu ----
    asplit_kernel<<<cblk, 256>>>(x, cnt4);
    wsplit_kernel<<<(256 * 256 + 255) / 256, 256>>>(W1, 256, 256 * 256);
    hmma_gemm_kernel<<<dim3(mtiles, 4), 256, 2 * STG_B>>>(hbuf, n, 256);
    scores_kernel<4, 64><<<warp_blocks, 256>>>(as1, ad1, n);
    agg_kernel<4, 64, 1><<<warp_blocks, 256>>>(b1, nullptr, n);  // writes g_ahi/g_alo

    // ---- layer 2: 256 -> 4x64, elu ----
    wsplit_kernel<<<(256 * 256 + 255) / 256, 256>>>(W2, 256, 256 * 256);
    hmma_gemm_kernel<<<dim3(mtiles, 4), 256, 2 * STG_B>>>(hbuf, n, 256);
    scores_kernel<4, 64><<<warp_blocks, 256>>>(as2, ad2, n);
    agg_kernel<4, 64, 1><<<warp_blocks, 256>>>(b2, nullptr, n);  // writes g_ahi/g_alo

    // ---- layer 3: 256 -> 1x128, no activation, write d_out ----
    wsplit_kernel<<<(256 * 128 + 255) / 256, 256>>>(W3, 128, 256 * 128);
    hmma_gemm_kernel<<<dim3(mtiles, 2), 256, 2 * STG_B>>>(hbuf, n, 128);
    scores_kernel<1, 128><<<warp_blocks, 256>>>(as3, ad3, n);
    agg_kernel<1, 128, 0><<<warp_blocks, 256>>>(b3, (float*)d_out, n);
}

// round 9
// speedup vs baseline: 1.6795x; 1.0281x over previous
#include <cuda_runtime.h>
#include <cuda_bf16.h>
#include <cstdint>
#include <cstddef>

// ---------------- problem constants ----------------
#define NMAX 50000
#define EMAX 800000
#define ETMAX (EMAX + NMAX)

// ---------------- device scratch ----------------
__device__ int   g_is64;
__device__ int   g_src[ETMAX];
__device__ int   g_dst[ETMAX];
__device__ int   g_cnt[NMAX];
__device__ int   g_rowptr[NMAX + 1];
__device__ int   g_cursor[NMAX];
__device__ int   g_part[64];
__device__ int   g_esrc[ETMAX];
__device__ float g_h[(size_t)NMAX * 256];    // GEMM output (per-layer features)
__device__ float g_as[(size_t)NMAX * 4];     // per-node src scores [N,H]
__device__ float g_ad[(size_t)NMAX * 4];     // per-node dst scores [N,H]
__device__ __nv_bfloat16 g_ahi[(size_t)NMAX * 256];  // A split hi (next GEMM input)
__device__ __nv_bfloat16 g_alo[(size_t)NMAX * 256];  // A split lo
__device__ __nv_bfloat16 g_bhi[256 * 256];           // W^T split hi [N,K]
__device__ __nv_bfloat16 g_blo[256 * 256];           // W^T split lo [N,K]

// =============================== CSR construction ==================================
__global__ void detect_kernel(const unsigned int* __restrict__ p, int E) {
    __shared__ int sor;
    if (threadIdx.x == 0) sor = 0;
    __syncthreads();
    int ns = E < 2048 ? E : 2048;
    unsigned int acc = 0;
    for (int i = threadIdx.x; i < ns; i += blockDim.x) acc |= p[2 * i + 1];
    if (acc) atomicOr(&sor, 1);
    __syncthreads();
    if (threadIdx.x == 0) g_is64 = (sor == 0) ? 1 : 0;
}
__global__ void zero_cnt_kernel(int n) {
    int i = blockIdx.x * blockDim.x + threadIdx.x;
    if (i < n) g_cnt[i] = 0;
}
__global__ void decode_count_kernel(const void* __restrict__ eptr, int E, int n) {
    int i = blockIdx.x * blockDim.x + threadIdx.x;
    int ET = E + n;
    if (i >= ET) return;
    int s, d;
    if (i >= E) {
        s = d = i - E;
    } else if (g_is64) {
        const long long* p = (const long long*)eptr;
        s = (int)p[i];
        d = (int)p[(size_t)E + i];
    } else {
        const int* p = (const int*)eptr;
        s = p[i];
        d = p[E + i];
    }
    g_src[i] = s;
    g_dst[i] = d;
    atomicAdd(&g_cnt[d], 1);
}
__global__ void scan1_kernel(int n) {
    __shared__ int sh[1024];
    int i = blockIdx.x * 1024 + threadIdx.x;
    int v = (i < n) ? g_cnt[i] : 0;
    sh[threadIdx.x] = v;
    __syncthreads();
    for (int o = 1; o < 1024; o <<= 1) {
        int t = (threadIdx.x >= o) ? sh[threadIdx.x - o] : 0;
        __syncthreads();
        sh[threadIdx.x] += t;
        __syncthreads();
    }
    if (i < n) g_rowptr[i + 1] = sh[threadIdx.x];
    if (threadIdx.x == 1023) g_part[blockIdx.x] = sh[1023];
}
__global__ void scan2_kernel(int nb) {
    int acc = 0;
    for (int i = 0; i < nb; i++) {
        int t = g_part[i];
        g_part[i] = acc;
        acc += t;
    }
}
__global__ void scan3_kernel(int n) {
    int i = blockIdx.x * blockDim.x + threadIdx.x;
    if (i < n) g_rowptr[i + 1] += g_part[i >> 10];
    if (i == 0) g_rowptr[0] = 0;
}
__global__ void cursor_kernel(int n) {
    int i = blockIdx.x * blockDim.x + threadIdx.x;
    if (i < n) g_cursor[i] = g_rowptr[i];
}
__global__ void scatter_kernel(int ET) {
    int i = blockIdx.x * blockDim.x + threadIdx.x;
    if (i >= ET) return;
    int d = g_dst[i];
    int pos = atomicAdd(&g_cursor[d], 1);
    g_esrc[pos] = g_src[i];
}

// ============================ split conversions ==================================
__global__ void asplit_kernel(const float* __restrict__ src, int count4) {
    int i = blockIdx.x * blockDim.x + threadIdx.x;
    if (i >= count4) return;
    float4 v = ((const float4*)src)[i];
    __nv_bfloat16 h0 = __float2bfloat16(v.x), h1 = __float2bfloat16(v.y);
    __nv_bfloat16 h2 = __float2bfloat16(v.z), h3 = __float2bfloat16(v.w);
    __nv_bfloat16 l0 = __float2bfloat16(v.x - __bfloat162float(h0));
    __nv_bfloat16 l1 = __float2bfloat16(v.y - __bfloat162float(h1));
    __nv_bfloat16 l2 = __float2bfloat16(v.z - __bfloat162float(h2));
    __nv_bfloat16 l3 = __float2bfloat16(v.w - __bfloat162float(h3));
    __nv_bfloat162* hp = (__nv_bfloat162*)g_ahi;
    __nv_bfloat162* lp = (__nv_bfloat162*)g_alo;
    hp[2 * i] = __nv_bfloat162(h0, h1);
    hp[2 * i + 1] = __nv_bfloat162(h2, h3);
    lp[2 * i] = __nv_bfloat162(l0, l1);
    lp[2 * i + 1] = __nv_bfloat162(l2, l3);
}
// W [K=256, N] fp32 -> W^T [N, 256] (hi, lo) bf16
__global__ void wsplit_kernel(const float* __restrict__ W, int N, int total) {
    int t = blockIdx.x * blockDim.x + threadIdx.x;
    if (t >= total) return;
    int k = t & 255, n = t >> 8;
    float v = W[(size_t)k * N + n];
    __nv_bfloat16 h = __float2bfloat16(v);
    g_bhi[n * 256 + k] = h;
    g_blo[n * 256 + k] = __float2bfloat16(v - __bfloat162float(h));
}
// zero the score accumulators (GEMM epilogue atomically accumulates into them)
__global__ void zero_scores_kernel(int cnt) {
    int i = blockIdx.x * blockDim.x + threadIdx.x;
    if (i < cnt) {
        g_as[i] = 0.f;
        g_ad[i] = 0.f;
    }
}

// ================= HMMA split-3 bf16 GEMM, cp.async double-buffered ================
// C[M, ldC] cols [n0, n0+64) = A[M,256] @ W[256, ldC]  (fp32 accum).
// Block 128x64, 8 warps (4x2), warp tile 32x32, BK=32. D = AhBh + AhBl + AlBh.
// Epilogue ALSO computes the attention-score partials ss = h.a_s, sd = h.a_d for
// this block's 64 columns (one head) and atomicAdds them into g_as/g_ad.
#define MMA_BF16(d, a, b)                                                              \
    asm volatile(                                                                       \
        "mma.sync.aligned.m16n8k16.row.col.f32.bf16.bf16.f32 "                          \
        "{%0,%1,%2,%3}, {%4,%5,%6,%7}, {%8,%9}, {%0,%1,%2,%3};"                         \
        : "+f"((d)[0]), "+f"((d)[1]), "+f"((d)[2]), "+f"((d)[3])                        \
        : "r"((a)[0]), "r"((a)[1]), "r"((a)[2]), "r"((a)[3]), "r"((b)[0]), "r"((b)[1]))

__device__ __forceinline__ void cp16(uint32_t dst, const void* src, int sz) {
    asm volatile("cp.async.cg.shared.global [%0], [%1], 16, %2;" :: "r"(dst), "l"(src),
                 "r"(sz) : "memory");
}

// stage layout (bytes): Ah 0 (10240), Al 10240, Bh 20480 (5120), Bl 25600; stage=30720
#define STG_B 30720

__global__ __launch_bounds__(256) void hmma_gemm_kernel(float* __restrict__ C, int M, int ldC,
                                                        const float* __restrict__ a_s,
                                                        const float* __restrict__ a_d,
                                                        int Cc, int H) {
    extern __shared__ __nv_bfloat16 sm[];
    int tid = threadIdx.x, wid = tid >> 5, lane = tid & 31;
    int warp_m = wid & 3, warp_n = wid >> 2;
    int g = lane >> 2, t = lane & 3;
    int m0 = blockIdx.x * 128, n0 = blockIdx.y * 64;
    uint32_t sbase = (uint32_t)__cvta_generic_to_shared(sm);

    float acc[2][4][4];
#pragma unroll
    for (int mt = 0; mt < 2; mt++)
#pragma unroll
        for (int nt = 0; nt < 4; nt++)
#pragma unroll
            for (int r = 0; r < 4; r++) acc[mt][nt][r] = 0.f;

    int arow0 = tid >> 2, aq = tid & 3;
    int brow = tid >> 2, bq = tid & 3;

    auto load_chunk = [&](int c, int stg) {
        int kc = c * 32;
        uint32_t base = sbase + stg * STG_B;
#pragma unroll
        for (int half = 0; half < 2; half++) {
            int row = arow0 + half * 64;
            int gr = m0 + row;
            int sz = (gr < M) ? 16 : 0;
            int grc = (gr < M) ? gr : 0;
            size_t go = (size_t)grc * 256 + kc + aq * 8;
            uint32_t so = base + (uint32_t)(row * 40 + aq * 8) * 2;
            cp16(so, g_ahi + go, sz);
            cp16(so + 10240, g_alo + go, sz);
        }
        {
            size_t go = (size_t)(n0 + brow) * 256 + kc + bq * 8;
            uint32_t so = base + 20480 + (uint32_t)(brow * 40 + bq * 8) * 2;
            cp16(so, g_bhi + go, 16);
            cp16(so + 5120, g_blo + go, 16);
        }
        asm volatile("cp.async.commit_group;" ::: "memory");
    };

    load_chunk(0, 0);

    for (int c = 0; c < 8; c++) {
        int stg = c & 1;
        if (c + 1 < 8) {
            load_chunk(c + 1, stg ^ 1);
            asm volatile("cp.async.wait_group 1;" ::: "memory");
        } else {
            asm volatile("cp.async.wait_group 0;" ::: "memory");
        }
        __syncthreads();

        const uint32_t* S = (const uint32_t*)((const char*)sm + stg * STG_B);
        const uint32_t* SAl = S + 2560;
        const uint32_t* SBh = S + 5120;
        const uint32_t* SBl = S + 6400;
#pragma unroll
        for (int kk = 0; kk < 32; kk += 16) {
            uint32_t ah[2][4], al[2][4], bh[4][2], bl[4][2];
#pragma unroll
            for (int mt = 0; mt < 2; mt++) {
                int r0 = warp_m * 32 + mt * 16 + g;
                int base = (r0 * 40 + kk + t * 2) >> 1;
                int base8 = ((r0 + 8) * 40 + kk + t * 2) >> 1;
                ah[mt][0] = S[base];
                ah[mt][1] = S[base8];
                ah[mt][2] = S[base + 4];
                ah[mt][3] = S[base8 + 4];
                al[mt][0] = SAl[base];
                al[mt][1] = SAl[base8];
                al[mt][2] = SAl[base + 4];
                al[mt][3] = SAl[base8 + 4];
            }
#pragma unroll
            for (int nt = 0; nt < 4; nt++) {
                int col = warp_n * 32 + nt * 8 + g;
                int base = (col * 40 + kk + t * 2) >> 1;
                bh[nt][0] = SBh[base];
                bh[nt][1] = SBh[base + 4];
                bl[nt][0] = SBl[base];
                bl[nt][1] = SBl[base + 4];
            }
#pragma unroll
            for (int mt = 0; mt < 2; mt++)
#pragma unroll
                for (int nt = 0; nt < 4; nt++) {
                    MMA_BF16(acc[mt][nt], ah[mt], bh[nt]);
                    MMA_BF16(acc[mt][nt], ah[mt], bl[nt]);
                    MMA_BF16(acc[mt][nt], al[mt], bh[nt]);
                }
        }
        __syncthreads();
    }

    // epilogue: store C + fused score partials
    int head = n0 / Cc;  // one block covers columns of exactly one head
#pragma unroll
    for (int mt = 0; mt < 2; mt++) {
        int r0 = m0 + warp_m * 32 + mt * 16 + g;
        float ss0 = 0.f, sd0 = 0.f, ss8 = 0.f, sd8 = 0.f;
#pragma unroll
        for (int nt = 0; nt < 4; nt++) {
            int col = n0 + warp_n * 32 + nt * 8 + t * 2;
            if (r0 < M)
                *(float2*)(C + (size_t)r0 * ldC + col) = make_float2(acc[mt][nt][0], acc[mt][nt][1]);
            if (r0 + 8 < M)
                *(float2*)(C + (size_t)(r0 + 8) * ldC + col) =
                    make_float2(acc[mt][nt][2], acc[mt][nt][3]);
            float a0 = a_s[col], a1 = a_s[col + 1];
            float d0 = a_d[col], d1 = a_d[col + 1];
            ss0 += acc[mt][nt][0] * a0 + acc[mt][nt][1] * a1;
            sd0 += acc[mt][nt][0] * d0 + acc[mt][nt][1] * d1;
            ss8 += acc[mt][nt][2] * a0 + acc[mt][nt][3] * a1;
            sd8 += acc[mt][nt][2] * d0 + acc[mt][nt][3] * d1;
        }
        // quad reduction over t (lanes g*4+t) -> sum over this warp's 32 columns
#pragma unroll
        for (int o = 1; o < 4; o <<= 1) {
            ss0 += __shfl_xor_sync(0xffffffffu, ss0, o);
            sd0 += __shfl_xor_sync(0xffffffffu, sd0, o);
            ss8 += __shfl_xor_sync(0xffffffffu, ss8, o);
            sd8 += __shfl_xor_sync(0xffffffffu, sd8, o);
        }
        if (t == 0) {
            if (r0 < M) {
                atomicAdd(&g_as[r0 * H + head], ss0);
                atomicAdd(&g_ad[r0 * H + head], sd0);
            }
            if (r0 + 8 < M) {
                atomicAdd(&g_as[(r0 + 8) * H + head], ss8);
                atomicAdd(&g_ad[(r0 + 8) * H + head], sd8);
            }
        }
    }
}

// ============== single-pass softmax + gather-aggregate (warp per node) =============
// out = (sum_e exp(lrelu(as[s]+ad[d])) * h[s]) / (sum_e exp(.) + eps)
// MODE 0: fp32 out (+bias). MODE 1: bias+ELU then split-write bf16 hi/lo to g_ahi/g_alo.
template <int H, int C, int MODE>
__global__ __launch_bounds__(256) void agg_kernel(const float* __restrict__ bias,
                                                  float* __restrict__ out, int n) {
    const int F = H * C, VC = F / 32, G = C / VC, NV4 = VC / 4;
    int gid = blockIdx.x * blockDim.x + threadIdx.x;
    int node = gid >> 5, lane = gid & 31;
    if (node >= n) return;
    int start = g_rowptr[node], end = g_rowptr[node + 1];
    int myh = lane / G;
    float adh = g_ad[node * H + myh];

    float den = 0.f;
    float4 acc[NV4];
#pragma unroll
    for (int i = 0; i < NV4; i++) acc[i] = make_float4(0.f, 0.f, 0.f, 0.f);
    const float4* HB = (const float4*)g_h;

    int e = start;
    for (; e + 1 < end; e += 2) {
        int s0 = g_esrc[e], s1 = g_esrc[e + 1];
        float v0 = g_as[s0 * H + myh] + adh;
        float v1 = g_as[s1 * H + myh] + adh;
        const float4* hp0 = HB + (size_t)s0 * (F / 4) + lane * NV4;
        const float4* hp1 = HB + (size_t)s1 * (F / 4) + lane * NV4;
        float4 t0[NV4], t1[NV4];
#pragma unroll
        for (int i = 0; i < NV4; i++) {
            t0[i] = hp0[i];
            t1[i] = hp1[i];
        }
        v0 = v0 > 0.f ? v0 : 0.2f * v0;
        v1 = v1 > 0.f ? v1 : 0.2f * v1;
        float w0 = __expf(v0), w1 = __expf(v1);
        den += w0 + w1;
#pragma unroll
        for (int i = 0; i < NV4; i++) {
            acc[i].x += w0 * t0[i].x + w1 * t1[i].x;
            acc[i].y += w0 * t0[i].y + w1 * t1[i].y;
            acc[i].z += w0 * t0[i].z + w1 * t1[i].z;
            acc[i].w += w0 * t0[i].w + w1 * t1[i].w;
        }
    }
    if (e < end) {
        int s = g_esrc[e];
        float v = g_as[s * H + myh] + adh;
        v = v > 0.f ? v : 0.2f * v;
        float w = __expf(v);
        den += w;
        const float4* hp = HB + (size_t)s * (F / 4) + lane * NV4;
#pragma unroll
        for (int i = 0; i < NV4; i++) {
            float4 hv = hp[i];
            acc[i].x += w * hv.x;
            acc[i].y += w * hv.y;
            acc[i].z += w * hv.z;
            acc[i].w += w * hv.w;
        }
    }
    float inv = 1.f / (den + 1e-16f);

    const float4* bp = (const float4*)bias + lane * NV4;
#pragma unroll
    for (int i = 0; i < NV4; i++) {
        float4 b4 = bp[i];
        float4 r = make_float4(acc[i].x * inv + b4.x, acc[i].y * inv + b4.y,
                               acc[i].z * inv + b4.z, acc[i].w * inv + b4.w);
        if (MODE == 0) {
            ((float4*)out)[(size_t)node * (F / 4) + lane * NV4 + i] = r;
        } else {
            r.x = r.x > 0.f ? r.x : __expf(r.x) - 1.f;
            r.y = r.y > 0.f ? r.y : __expf(r.y) - 1.f;
            r.z = r.z > 0.f ? r.z : __expf(r.z) - 1.f;
            r.w = r.w > 0.f ? r.w : __expf(r.w) - 1.f;
            __nv_bfloat16 h0 = __float2bfloat16(r.x), h1 = __float2bfloat16(r.y);
            __nv_bfloat16 h2 = __float2bfloat16(r.z), h3 = __float2bfloat16(r.w);
            __nv_bfloat16 l0 = __float2bfloat16(r.x - __bfloat162float(h0));
            __nv_bfloat16 l1 = __float2bfloat16(r.y - __bfloat162float(h1));
            __nv_bfloat16 l2 = __float2bfloat16(r.z - __bfloat162float(h2));
            __nv_bfloat16 l3 = __float2bfloat16(r.w - __bfloat162float(h3));
            size_t ch = (size_t)node * F + lane * VC + i * 4;
            *(__nv_bfloat162*)(g_ahi + ch) = __nv_bfloat162(h0, h1);
            *(__nv_bfloat162*)(g_ahi + ch + 2) = __nv_bfloat162(h2, h3);
            *(__nv_bfloat162*)(g_alo + ch) = __nv_bfloat162(l0, l1);
            *(__nv_bfloat162*)(g_alo + ch + 2) = __nv_bfloat162(l2, l3);
        }
    }
}

// =================================== host side =====================================
extern "C" void kernel_launch(void* const* d_in, const int* in_sizes, int n_in,
                              void* d_out, int out_size) {
    const float* x = (const float*)d_in[0];
    const void* eidx = d_in[1];
    const float* W1 = (const float*)d_in[2];
    const float* as1 = (const float*)d_in[3];
    const float* ad1 = (const float*)d_in[4];
    const float* b1 = (const float*)d_in[5];
    const float* W2 = (const float*)d_in[6];
    const float* as2 = (const float*)d_in[7];
    const float* ad2 = (const float*)d_in[8];
    const float* b2 = (const float*)d_in[9];
    const float* W3 = (const float*)d_in[10];
    const float* as3 = (const float*)d_in[11];
    const float* ad3 = (const float*)d_in[12];
    const float* b3 = (const float*)d_in[13];

    int n = in_sizes[0] / 256;
    int E = in_sizes[1] / 2;
    int ET = E + n;

    float* hbuf = nullptr;
    cudaGetSymbolAddress((void**)&hbuf, g_h);

    cudaFuncSetAttribute(hmma_gemm_kernel, cudaFuncAttributeMaxDynamicSharedMemorySize,
                         2 * STG_B);

    int nb = (n + 1023) / 1024;

    // ---- CSR build (graph identical across layers) ----
    detect_kernel<<<1, 1024>>>((const unsigned int*)eidx, E);
    zero_cnt_kernel<<<(n + 255) / 256, 256>>>(n);
    decode_count_kernel<<<(ET + 255) / 256, 256>>>(eidx, E, n);
    scan1_kernel<<<nb, 1024>>>(n);
    scan2_kernel<<<1, 1>>>(nb);
    scan3_kernel<<<(n + 255) / 256, 256>>>(n);
    cursor_kernel<<<(n + 255) / 256, 256>>>(n);
    scatter_kernel<<<(ET + 255) / 256, 256>>>(ET);

    int warp_blocks = (n * 32 + 255) / 256;
    int cnt4 = n * 64;
    int cblk = (cnt4 + 255) / 256;
    int mtiles = (n + 127) / 128;
    int zs4 = (n * 4 + 255) / 256;
    int zs1 = (n + 255) / 256;

    // ---- layer 1: 256 -> 4x64, elu ----
    asplit_kernel<<<cblk, 256>>>(x, cnt4);
    wsplit_kernel<<<(256 * 256 + 255) / 256, 256>>>(W1, 256, 256 * 256);
    zero_scores_kernel<<<zs4, 256>>>(n * 4);
    hmma_gemm_kernel<<<dim3(mtiles, 4), 256, 2 * STG_B>>>(hbuf, n, 256, as1, ad1, 64, 4);
    agg_kernel<4, 64, 1><<<warp_blocks, 256>>>(b1, nullptr, n);  // writes g_ahi/g_alo

    // ---- layer 2: 256 -> 4x64, elu ----
    wsplit_kernel<<<(256 * 256 + 255) / 256, 256>>>(W2, 256, 256 * 256);
    zero_scores_kernel<<<zs4, 256>>>(n * 4);
    hmma_gemm_kernel<<<dim3(mtiles, 4), 256, 2 * STG_B>>>(hbuf, n, 256, as2, ad2, 64, 4);
    agg_kernel<4, 64, 1><<<warp_blocks, 256>>>(b2, nullptr, n);  // writes g_ahi/g_alo

    // ---- layer 3: 256 -> 1x128, no activation, write d_out ----
    wsplit_kernel<<<(256 * 128 + 255) / 256, 256>>>(W3, 128, 256 * 128);
    zero_scores_kernel<<<zs1, 256>>>(n);
    hmma_gemm_kernel<<<dim3(mtiles, 2), 256, 2 * STG_B>>>(hbuf, n, 128, as3, ad3, 128, 1);
    agg_kernel<1, 128, 0><<<warp_blocks, 256>>>(b3, (float*)d_out, n);
}

// round 11
// speedup vs baseline: 1.7949x; 1.0687x over previous
#include <cuda_runtime.h>
#include <cuda_bf16.h>
#include <cstdint>
#include <cstddef>

// ---------------- problem constants ----------------
#define NMAX 50000
#define EMAX 800000
#define ETMAX (EMAX + NMAX)

// ---------------- device scratch ----------------
__device__ int   g_is64;
__device__ int   g_src[ETMAX];
__device__ int   g_dst[ETMAX];
__device__ int   g_cnt[NMAX];
__device__ int   g_rowptr[NMAX + 1];
__device__ int   g_cursor[NMAX];
__device__ int   g_part[64];
__device__ int   g_esrc[ETMAX];
__device__ float g_h[(size_t)NMAX * 256];    // GEMM output (per-layer features)
__device__ float g_as[(size_t)NMAX * 4];     // per-node src scores [N,H]
__device__ float g_ad[(size_t)NMAX * 4];     // per-node dst scores [N,H]
__device__ __nv_bfloat16 g_ahi[(size_t)NMAX * 256];  // A split hi (next GEMM input)
__device__ __nv_bfloat16 g_alo[(size_t)NMAX * 256];  // A split lo
__device__ __nv_bfloat16 g_bhi[256 * 256];           // W^T split hi [N,K]
__device__ __nv_bfloat16 g_blo[256 * 256];           // W^T split lo [N,K]

// =============================== CSR construction ==================================
__global__ void detect_kernel(const unsigned int* __restrict__ p, int E) {
    __shared__ int sor;
    if (threadIdx.x == 0) sor = 0;
    __syncthreads();
    int ns = E < 2048 ? E : 2048;
    unsigned int acc = 0;
    for (int i = threadIdx.x; i < ns; i += blockDim.x) acc |= p[2 * i + 1];
    if (acc) atomicOr(&sor, 1);
    __syncthreads();
    if (threadIdx.x == 0) g_is64 = (sor == 0) ? 1 : 0;
}
__global__ void zero_cnt_kernel(int n) {
    int i = blockIdx.x * blockDim.x + threadIdx.x;
    if (i < n) g_cnt[i] = 0;
}
__global__ void decode_count_kernel(const void* __restrict__ eptr, int E, int n) {
    int i = blockIdx.x * blockDim.x + threadIdx.x;
    int ET = E + n;
    if (i >= ET) return;
    int s, d;
    if (i >= E) {
        s = d = i - E;
    } else if (g_is64) {
        const long long* p = (const long long*)eptr;
        s = (int)p[i];
        d = (int)p[(size_t)E + i];
    } else {
        const int* p = (const int*)eptr;
        s = p[i];
        d = p[E + i];
    }
    g_src[i] = s;
    g_dst[i] = d;
    atomicAdd(&g_cnt[d], 1);
}
__global__ void scan1_kernel(int n) {
    __shared__ int sh[1024];
    int i = blockIdx.x * 1024 + threadIdx.x;
    int v = (i < n) ? g_cnt[i] : 0;
    sh[threadIdx.x] = v;
    __syncthreads();
    for (int o = 1; o < 1024; o <<= 1) {
        int t = (threadIdx.x >= o) ? sh[threadIdx.x - o] : 0;
        __syncthreads();
        sh[threadIdx.x] += t;
        __syncthreads();
    }
    if (i < n) g_rowptr[i + 1] = sh[threadIdx.x];
    if (threadIdx.x == 1023) g_part[blockIdx.x] = sh[1023];
}
__global__ void scan2_kernel(int nb) {
    int acc = 0;
    for (int i = 0; i < nb; i++) {
        int t = g_part[i];
        g_part[i] = acc;
        acc += t;
    }
}
__global__ void scan3_kernel(int n) {
    int i = blockIdx.x * blockDim.x + threadIdx.x;
    if (i < n) g_rowptr[i + 1] += g_part[i >> 10];
    if (i == 0) g_rowptr[0] = 0;
}
__global__ void cursor_kernel(int n) {
    int i = blockIdx.x * blockDim.x + threadIdx.x;
    if (i < n) g_cursor[i] = g_rowptr[i];
}
__global__ void scatter_kernel(int ET) {
    int i = blockIdx.x * blockDim.x + threadIdx.x;
    if (i >= ET) return;
    int d = g_dst[i];
    int pos = atomicAdd(&g_cursor[d], 1);
    g_esrc[pos] = g_src[i];
}

// ============================ split conversions ==================================
__global__ void asplit_kernel(const float* __restrict__ src, int count4) {
    int i = blockIdx.x * blockDim.x + threadIdx.x;
    if (i >= count4) return;
    float4 v = ((const float4*)src)[i];
    __nv_bfloat16 h0 = __float2bfloat16(v.x), h1 = __float2bfloat16(v.y);
    __nv_bfloat16 h2 = __float2bfloat16(v.z), h3 = __float2bfloat16(v.w);
    __nv_bfloat16 l0 = __float2bfloat16(v.x - __bfloat162float(h0));
    __nv_bfloat16 l1 = __float2bfloat16(v.y - __bfloat162float(h1));
    __nv_bfloat16 l2 = __float2bfloat16(v.z - __bfloat162float(h2));
    __nv_bfloat16 l3 = __float2bfloat16(v.w - __bfloat162float(h3));
    __nv_bfloat162* hp = (__nv_bfloat162*)g_ahi;
    __nv_bfloat162* lp = (__nv_bfloat162*)g_alo;
    hp[2 * i] = __nv_bfloat162(h0, h1);
    hp[2 * i + 1] = __nv_bfloat162(h2, h3);
    lp[2 * i] = __nv_bfloat162(l0, l1);
    lp[2 * i + 1] = __nv_bfloat162(l2, l3);
}
// W [K=256, N] fp32 -> W^T [N, 256] (hi, lo) bf16
__global__ void wsplit_kernel(const float* __restrict__ W, int N, int total) {
    int t = blockIdx.x * blockDim.x + threadIdx.x;
    if (t >= total) return;
    int k = t & 255, n = t >> 8;
    float v = W[(size_t)k * N + n];
    __nv_bfloat16 h = __float2bfloat16(v);
    g_bhi[n * 256 + k] = h;
    g_blo[n * 256 + k] = __float2bfloat16(v - __bfloat162float(h));
}
// zero the score accumulators (GEMM epilogue atomically accumulates into them)
__global__ void zero_scores_kernel(int cnt) {
    int i = blockIdx.x * blockDim.x + threadIdx.x;
    if (i < cnt) {
        g_as[i] = 0.f;
        g_ad[i] = 0.f;
    }
}

// ========== HMMA split-3 bf16 GEMM: 3-stage cp.async + ldmatrix fragments ==========
// C[M, ldC] cols [n0, n0+64) = A[M,256] @ W[256, ldC]  (fp32 accum).
// Block 128x64, 8 warps (4x2), warp tile 32x32, BK=32. D = AhBh + AhBl + AlBh.
// Epilogue fuses the attention-score partials into g_as/g_ad via atomics.
#define MMA_BF16(d, a, b)                                                              \
    asm volatile(                                                                       \
        "mma.sync.aligned.m16n8k16.row.col.f32.bf16.bf16.f32 "                          \
        "{%0,%1,%2,%3}, {%4,%5,%6,%7}, {%8,%9}, {%0,%1,%2,%3};"                         \
        : "+f"((d)[0]), "+f"((d)[1]), "+f"((d)[2]), "+f"((d)[3])                        \
        : "r"((a)[0]), "r"((a)[1]), "r"((a)[2]), "r"((a)[3]), "r"((b)[0]), "r"((b)[1]))

#define LDSM_X4(r, addr)                                                               \
    asm volatile("ldmatrix.sync.aligned.m8n8.x4.shared.b16 {%0,%1,%2,%3}, [%4];"       \
                 : "=r"((r)[0]), "=r"((r)[1]), "=r"((r)[2]), "=r"((r)[3])              \
                 : "r"(addr))

__device__ __forceinline__ void cp16(uint32_t dst, const void* src, int sz) {
    asm volatile("cp.async.cg.shared.global [%0], [%1], 16, %2;" :: "r"(dst), "l"(src),
                 "r"(sz) : "memory");
}

// stage layout (bytes): Ah 0 (10240), Al 10240, Bh 20480 (5120), Bl 25600; stage=30720
#define STG_B 30720
#define NSTG 3

__global__ __launch_bounds__(256) void hmma_gemm_kernel(float* __restrict__ C, int M, int ldC,
                                                        const float* __restrict__ a_s,
                                                        const float* __restrict__ a_d,
                                                        int Cc, int H) {
    extern __shared__ char sm[];
    int tid = threadIdx.x, wid = tid >> 5, lane = tid & 31;
    int warp_m = wid & 3, warp_n = wid >> 2;
    int g = lane >> 2, t = lane & 3;
    int m0 = blockIdx.x * 128, n0 = blockIdx.y * 64;
    uint32_t sbase = (uint32_t)__cvta_generic_to_shared(sm);

    float acc[2][4][4];
#pragma unroll
    for (int mt = 0; mt < 2; mt++)
#pragma unroll
        for (int nt = 0; nt < 4; nt++)
#pragma unroll
            for (int r = 0; r < 4; r++) acc[mt][nt][r] = 0.f;

    int arow0 = tid >> 2, aq = tid & 3;
    int brow = tid >> 2, bq = tid & 3;

    auto load_chunk = [&](int c, int stg) {
        int kc = c * 32;
        uint32_t base = sbase + stg * STG_B;
#pragma unroll
        for (int half = 0; half < 2; half++) {
            int row = arow0 + half * 64;
            int gr = m0 + row;
            int sz = (gr < M) ? 16 : 0;
            int grc = (gr < M) ? gr : 0;
            size_t go = (size_t)grc * 256 + kc + aq * 8;
            uint32_t so = base + (uint32_t)(row * 40 + aq * 8) * 2;
            cp16(so, g_ahi + go, sz);
            cp16(so + 10240, g_alo + go, sz);
        }
        {
            size_t go = (size_t)(n0 + brow) * 256 + kc + bq * 8;
            uint32_t so = base + 20480 + (uint32_t)(brow * 40 + bq * 8) * 2;
            cp16(so, g_bhi + go, 16);
            cp16(so + 5120, g_blo + go, 16);
        }
        asm volatile("cp.async.commit_group;" ::: "memory");
    };

    // ldmatrix per-thread address offsets (bytes within a stage)
    // A frag (m16k16, x4): rows r0+(lane&15), col kk + (lane>>4)*8
    uint32_t aoff[2];
#pragma unroll
    for (int mt = 0; mt < 2; mt++) {
        int row = warp_m * 32 + mt * 16 + (lane & 15);
        aoff[mt] = (uint32_t)(row * 40 + ((lane >> 4) & 1) * 8) * 2;
    }
    // B frag pair (2 x m8k16, x4): rows base + ((lane>>4)&1)*8 + (lane&7),
    // col kk + ((lane>>3)&1)*8
    uint32_t boff[2];
#pragma unroll
    for (int ntp = 0; ntp < 2; ntp++) {
        int row = warp_n * 32 + ntp * 16 + ((lane >> 4) & 1) * 8 + (lane & 7);
        boff[ntp] = 20480u + (uint32_t)(row * 40 + ((lane >> 3) & 1) * 8) * 2;
    }

    load_chunk(0, 0);
    load_chunk(1, 1);

    for (int c = 0; c < 8; c++) {
        int stg = c % NSTG;
        if (c < 7)
            asm volatile("cp.async.wait_group 1;" ::: "memory");
        else
            asm volatile("cp.async.wait_group 0;" ::: "memory");
        __syncthreads();
        if (c + 2 < 8) load_chunk(c + 2, (c + 2) % NSTG);

        uint32_t stbase = sbase + stg * STG_B;
#pragma unroll
        for (int kk = 0; kk < 32; kk += 16) {
            uint32_t ah[2][4], al[2][4], bh[4][2], bl[4][2];
#pragma unroll
            for (int mt = 0; mt < 2; mt++) {
                uint32_t ad = stbase + aoff[mt] + kk * 2;
                LDSM_X4(ah[mt], ad);
                LDSM_X4(al[mt], ad + 10240);
            }
#pragma unroll
            for (int ntp = 0; ntp < 2; ntp++) {
                uint32_t bd = stbase + boff[ntp] + kk * 2;
                uint32_t rh[4], rl[4];
                LDSM_X4(rh, bd);
                LDSM_X4(rl, bd + 5120);
                bh[2 * ntp][0] = rh[0];
                bh[2 * ntp][1] = rh[1];
                bh[2 * ntp + 1][0] = rh[2];
                bh[2 * ntp + 1][1] = rh[3];
                bl[2 * ntp][0] = rl[0];
                bl[2 * ntp][1] = rl[1];
                bl[2 * ntp + 1][0] = rl[2];
                bl[2 * ntp + 1][1] = rl[3];
            }
#pragma unroll
            for (int mt = 0; mt < 2; mt++)
#pragma unroll
                for (int nt = 0; nt < 4; nt++) {
                    MMA_BF16(acc[mt][nt], ah[mt], bh[nt]);
                    MMA_BF16(acc[mt][nt], ah[mt], bl[nt]);
                    MMA_BF16(acc[mt][nt], al[mt], bh[nt]);
                }
        }
    }

    // epilogue: store C + fused score partials
    int head = n0 / Cc;  // one block covers columns of exactly one head
#pragma unroll
    for (int mt = 0; mt < 2; mt++) {
        int r0 = m0 + warp_m * 32 + mt * 16 + g;
        float ss0 = 0.f, sd0 = 0.f, ss8 = 0.f, sd8 = 0.f;
#pragma unroll
        for (int nt = 0; nt < 4; nt++) {
            int col = n0 + warp_n * 32 + nt * 8 + t * 2;
            if (r0 < M)
                *(float2*)(C + (size_t)r0 * ldC + col) = make_float2(acc[mt][nt][0], acc[mt][nt][1]);
            if (r0 + 8 < M)
                *(float2*)(C + (size_t)(r0 + 8) * ldC + col) =
                    make_float2(acc[mt][nt][2], acc[mt][nt][3]);
            float a0 = a_s[col], a1 = a_s[col + 1];
            float d0 = a_d[col], d1 = a_d[col + 1];
            ss0 += acc[mt][nt][0] * a0 + acc[mt][nt][1] * a1;
            sd0 += acc[mt][nt][0] * d0 + acc[mt][nt][1] * d1;
            ss8 += acc[mt][nt][2] * a0 + acc[mt][nt][3] * a1;
            sd8 += acc[mt][nt][2] * d0 + acc[mt][nt][3] * d1;
        }
#pragma unroll
        for (int o = 1; o < 4; o <<= 1) {
            ss0 += __shfl_xor_sync(0xffffffffu, ss0, o);
            sd0 += __shfl_xor_sync(0xffffffffu, sd0, o);
            ss8 += __shfl_xor_sync(0xffffffffu, ss8, o);
            sd8 += __shfl_xor_sync(0xffffffffu, sd8, o);
        }
        if (t == 0) {
            if (r0 < M) {
                atomicAdd(&g_as[r0 * H + head], ss0);
                atomicAdd(&g_ad[r0 * H + head], sd0);
            }
            if (r0 + 8 < M) {
                atomicAdd(&g_as[(r0 + 8) * H + head], ss8);
                atomicAdd(&g_ad[(r0 + 8) * H + head], sd8);
            }
        }
    }
}

// ============== single-pass softmax + gather-aggregate (warp per node) =============
// out = (sum_e exp(lrelu(as[s]+ad[d])) * h[s]) / (sum_e exp(.) + eps)
// MODE 0: fp32 out (+bias). MODE 1: bias+ELU then split-write bf16 hi/lo to g_ahi/g_alo.
template <int H, int C, int MODE>
__global__ __launch_bounds__(256) void agg_kernel(const float* __restrict__ bias,
                                                  float* __restrict__ out, int n) {
    const int F = H * C, VC = F / 32, G = C / VC, NV4 = VC / 4;
    int gid = blockIdx.x * blockDim.x + threadIdx.x;
    int node = gid >> 5, lane = gid & 31;
    if (node >= n) return;
    int start = g_rowptr[node], end = g_rowptr[node + 1];
    int myh = lane / G;
    float adh = g_ad[node * H + myh];

    float den = 0.f;
    float4 acc[NV4];
#pragma unroll
    for (int i = 0; i < NV4; i++) acc[i] = make_float4(0.f, 0.f, 0.f, 0.f);
    const float4* HB = (const float4*)g_h;

    int e = start;
    for (; e + 1 < end; e += 2) {
        int s0 = g_esrc[e], s1 = g_esrc[e + 1];
        float v0 = g_as[s0 * H + myh] + adh;
        float v1 = g_as[s1 * H + myh] + adh;
        const float4* hp0 = HB + (size_t)s0 * (F / 4) + lane * NV4;
        const float4* hp1 = HB + (size_t)s1 * (F / 4) + lane * NV4;
        float4 t0[NV4], t1[NV4];
#pragma unroll
        for (int i = 0; i < NV4; i++) {
            t0[i] = hp0[i];
            t1[i] = hp1[i];
        }
        v0 = v0 > 0.f ? v0 : 0.2f * v0;
        v1 = v1 > 0.f ? v1 : 0.2f * v1;
        float w0 = __expf(v0), w1 = __expf(v1);
        den += w0 + w1;
#pragma unroll
        for (int i = 0; i < NV4; i++) {
            acc[i].x += w0 * t0[i].x + w1 * t1[i].x;
            acc[i].y += w0 * t0[i].y + w1 * t1[i].y;
            acc[i].z += w0 * t0[i].z + w1 * t1[i].z;
            acc[i].w += w0 * t0[i].w + w1 * t1[i].w;
        }
    }
    if (e < end) {
        int s = g_esrc[e];
        float v = g_as[s * H + myh] + adh;
        v = v > 0.f ? v : 0.2f * v;
        float w = __expf(v);
        den += w;
        const float4* hp = HB + (size_t)s * (F / 4) + lane * NV4;
#pragma unroll
        for (int i = 0; i < NV4; i++) {
            float4 hv = hp[i];
            acc[i].x += w * hv.x;
            acc[i].y += w * hv.y;
            acc[i].z += w * hv.z;
            acc[i].w += w * hv.w;
        }
    }
    float inv = 1.f / (den + 1e-16f);

    const float4* bp = (const float4*)bias + lane * NV4;
#pragma unroll
    for (int i = 0; i < NV4; i++) {
        float4 b4 = bp[i];
        float4 r = make_float4(acc[i].x * inv + b4.x, acc[i].y * inv + b4.y,
                               acc[i].z * inv + b4.z, acc[i].w * inv + b4.w);
        if (MODE == 0) {
            ((float4*)out)[(size_t)node * (F / 4) + lane * NV4 + i] = r;
        } else {
            r.x = r.x > 0.f ? r.x : __expf(r.x) - 1.f;
            r.y = r.y > 0.f ? r.y : __expf(r.y) - 1.f;
            r.z = r.z > 0.f ? r.z : __expf(r.z) - 1.f;
            r.w = r.w > 0.f ? r.w : __expf(r.w) - 1.f;
            __nv_bfloat16 h0 = __float2bfloat16(r.x), h1 = __float2bfloat16(r.y);
            __nv_bfloat16 h2 = __float2bfloat16(r.z), h3 = __float2bfloat16(r.w);
            __nv_bfloat16 l0 = __float2bfloat16(r.x - __bfloat162float(h0));
            __nv_bfloat16 l1 = __float2bfloat16(r.y - __bfloat162float(h1));
            __nv_bfloat16 l2 = __float2bfloat16(r.z - __bfloat162float(h2));
            __nv_bfloat16 l3 = __float2bfloat16(r.w - __bfloat162float(h3));
            size_t ch = (size_t)node * F + lane * VC + i * 4;
            *(__nv_bfloat162*)(g_ahi + ch) = __nv_bfloat162(h0, h1);
            *(__nv_bfloat162*)(g_ahi + ch + 2) = __nv_bfloat162(h2, h3);
            *(__nv_bfloat162*)(g_alo + ch) = __nv_bfloat162(l0, l1);
            *(__nv_bfloat162*)(g_alo + ch + 2) = __nv_bfloat162(l2, l3);
        }
    }
}

// =================================== host side =====================================
extern "C" void kernel_launch(void* const* d_in, const int* in_sizes, int n_in,
                              void* d_out, int out_size) {
    const float* x = (const float*)d_in[0];
    const void* eidx = d_in[1];
    const float* W1 = (const float*)d_in[2];
    const float* as1 = (const float*)d_in[3];
    const float* ad1 = (const float*)d_in[4];
    const float* b1 = (const float*)d_in[5];
    const float* W2 = (const float*)d_in[6];
    const float* as2 = (const float*)d_in[7];
    const float* ad2 = (const float*)d_in[8];
    const float* b2 = (const float*)d_in[9];
    const float* W3 = (const float*)d_in[10];
    const float* as3 = (const float*)d_in[11];
    const float* ad3 = (const float*)d_in[12];
    const float* b3 = (const float*)d_in[13];

    int n = in_sizes[0] / 256;
    int E = in_sizes[1] / 2;
    int ET = E + n;

    float* hbuf = nullptr;
    cudaGetSymbolAddress((void**)&hbuf, g_h);

    cudaFuncSetAttribute(hmma_gemm_kernel, cudaFuncAttributeMaxDynamicSharedMemorySize,
                         NSTG * STG_B);

    int nb = (n + 1023) / 1024;

    // ---- CSR build (graph identical across layers) ----
    detect_kernel<<<1, 1024>>>((const unsigned int*)eidx, E);
    zero_cnt_kernel<<<(n + 255) / 256, 256>>>(n);
    decode_count_kernel<<<(ET + 255) / 256, 256>>>(eidx, E, n);
    scan1_kernel<<<nb, 1024>>>(n);
    scan2_kernel<<<1, 1>>>(nb);
    scan3_kernel<<<(n + 255) / 256, 256>>>(n);
    cursor_kernel<<<(n + 255) / 256, 256>>>(n);
    scatter_kernel<<<(ET + 255) / 256, 256>>>(ET);

    int warp_blocks = (n * 32 + 255) / 256;
    int cnt4 = n * 64;
    int cblk = (cnt4 + 255) / 256;
    int mtiles = (n + 127) / 128;
    int zs4 = (n * 4 + 255) / 256;
    int zs1 = (n + 255) / 256;

    // ---- layer 1: 256 -> 4x64, elu ----
    asplit_kernel<<<cblk, 256>>>(x, cnt4);
    wsplit_kernel<<<(256 * 256 + 255) / 256, 256>>>(W1, 256, 256 * 256);
    zero_scores_kernel<<<zs4, 256>>>(n * 4);
    hmma_gemm_kernel<<<dim3(mtiles, 4), 256, NSTG * STG_B>>>(hbuf, n, 256, as1, ad1, 64, 4);
    agg_kernel<4, 64, 1><<<warp_blocks, 256>>>(b1, nullptr, n);  // writes g_ahi/g_alo

    // ---- layer 2: 256 -> 4x64, elu ----
    wsplit_kernel<<<(256 * 256 + 255) / 256, 256>>>(W2, 256, 256 * 256);
    zero_scores_kernel<<<zs4, 256>>>(n * 4);
    hmma_gemm_kernel<<<dim3(mtiles, 4), 256, NSTG * STG_B>>>(hbuf, n, 256, as2, ad2, 64, 4);
    agg_kernel<4, 64, 1><<<warp_blocks, 256>>>(b2, nullptr, n);  // writes g_ahi/g_alo

    // ---- layer 3: 256 -> 1x128, no activation, write d_out ----
    wsplit_kernel<<<(256 * 128 + 255) / 256, 256>>>(W3, 128, 256 * 128);
    zero_scores_kernel<<<zs1, 256>>>(n);
    hmma_gemm_kernel<<<dim3(mtiles, 2), 256, NSTG * STG_B>>>(hbuf, n, 128, as3, ad3, 128, 1);
    agg_kernel<1, 128, 0><<<warp_blocks, 256>>>(b3, (float*)d_out, n);
}